// round 1
// baseline (speedup 1.0000x reference)
#include <cuda_runtime.h>
#include <math.h>

#define N_NODES   50000
#define N_HE      20000
#define N_PAIRS   400000
#define E_EDGES   800000
#define L_EDGES   100000

// ---------------- scratch (device globals; no runtime allocation) ----------------
__device__ float    g_h0 [N_NODES * 256];   // x @ W1
__device__ float    g_m  [N_HE    * 256];   // hyperedge messages
__device__ float    g_h1 [N_NODES * 256];   // relu(hconv) ; reused for h2
__device__ float    g_hg [N_NODES * 256];   // GAT transformed features
__device__ float    g_acc[N_NODES * 256];   // aggregation accumulator
__device__ float    g_D  [N_NODES];
__device__ float    g_B  [N_HE];
__device__ float    g_as [N_NODES];
__device__ float    g_ad [N_NODES];
__device__ unsigned g_mx [N_NODES];
__device__ float    g_sm [N_NODES];
__device__ float    g_z  [N_NODES * 64];

// ---------------- helpers ----------------
__device__ __forceinline__ float dec_key(unsigned k) {
    k = (k & 0x80000000u) ? (k ^ 0x80000000u) : ~k;
    return __uint_as_float(k);
}
__device__ __forceinline__ unsigned enc_key(float f) {
    unsigned k = __float_as_uint(f);
    return (k & 0x80000000u) ? ~k : (k | 0x80000000u);
}
__device__ __forceinline__ float lrelu02(float x) { return x > 0.f ? x : 0.2f * x; }

// ---------------- GEMM: C[M,N] = A[M,K] @ B[K,N], row-major fp32 ----------------
#define BM 64
#define BN 64
#define BK 16
__global__ __launch_bounds__(256)
void sgemm_k(const float* __restrict__ A, const float* __restrict__ B,
             float* __restrict__ C, int M, int N, int K) {
    __shared__ float As[BK][BM + 1];
    __shared__ float Bs[BK][BN + 1];
    const int tid = threadIdx.x;
    const int tx = tid & 15, ty = tid >> 4;
    const int rowBase = blockIdx.y * BM, colBase = blockIdx.x * BN;
    float acc[4][4] = {};
    for (int k0 = 0; k0 < K; k0 += BK) {
        #pragma unroll
        for (int i = tid; i < BM * BK; i += 256) {
            int r = i >> 4, c = i & 15;
            int gr = rowBase + r;
            As[c][r] = (gr < M) ? A[(size_t)gr * K + k0 + c] : 0.f;
        }
        #pragma unroll
        for (int i = tid; i < BK * BN; i += 256) {
            int r = i >> 6, c = i & 63;
            Bs[r][c] = B[(size_t)(k0 + r) * N + colBase + c];
        }
        __syncthreads();
        #pragma unroll
        for (int k = 0; k < BK; k++) {
            float a[4], b[4];
            #pragma unroll
            for (int i = 0; i < 4; i++) a[i] = As[k][ty * 4 + i];
            #pragma unroll
            for (int j = 0; j < 4; j++) b[j] = Bs[k][tx * 4 + j];
            #pragma unroll
            for (int i = 0; i < 4; i++)
                #pragma unroll
                for (int j = 0; j < 4; j++) acc[i][j] += a[i] * b[j];
        }
        __syncthreads();
    }
    #pragma unroll
    for (int i = 0; i < 4; i++) {
        int gr = rowBase + ty * 4 + i;
        if (gr < M) {
            #pragma unroll
            for (int j = 0; j < 4; j++)
                C[(size_t)gr * N + colBase + tx * 4 + j] = acc[i][j];
        }
    }
}

// ---------------- hypergraph conv ----------------
__global__ void k_count(const int* __restrict__ hn, const int* __restrict__ he) {
    int i = blockIdx.x * blockDim.x + threadIdx.x;
    if (i < N_PAIRS) {
        atomicAdd(&g_D[hn[i]], 1.f);
        atomicAdd(&g_B[he[i]], 1.f);
    }
}
// node -> hyperedge scatter (warp per pair, 256 channels)
__global__ void k_hc_scatter_m(const int* __restrict__ hn, const int* __restrict__ he) {
    int gw = (blockIdx.x * blockDim.x + threadIdx.x) >> 5;
    int lane = threadIdx.x & 31;
    if (gw >= N_PAIRS) return;
    int n = hn[gw], e = he[gw];
    const float* src = g_h0 + (size_t)n * 256;
    float* dst = g_m + (size_t)e * 256;
    #pragma unroll
    for (int j = 0; j < 8; j++)
        atomicAdd(&dst[lane + 32 * j], src[lane + 32 * j]);
}
__global__ void k_scale_m() {
    int idx = blockIdx.x * blockDim.x + threadIdx.x;
    if (idx < N_HE * 256) {
        float b = g_B[idx >> 8];
        g_m[idx] *= (b > 0.f ? 1.f / b : 0.f);
    }
}
// hyperedge -> node scatter
__global__ void k_hc_scatter_n(const int* __restrict__ hn, const int* __restrict__ he) {
    int gw = (blockIdx.x * blockDim.x + threadIdx.x) >> 5;
    int lane = threadIdx.x & 31;
    if (gw >= N_PAIRS) return;
    int n = hn[gw], e = he[gw];
    const float* src = g_m + (size_t)e * 256;
    float* dst = g_acc + (size_t)n * 256;
    #pragma unroll
    for (int j = 0; j < 8; j++)
        atomicAdd(&dst[lane + 32 * j], src[lane + 32 * j]);
}
__global__ void k_hc_finish(const float* __restrict__ b1) {
    int idx = blockIdx.x * blockDim.x + threadIdx.x;
    if (idx < N_NODES * 256) {
        float d = g_D[idx >> 8];
        float dinv = d > 0.f ? 1.f / d : 0.f;
        g_h1[idx] = fmaxf(dinv * g_acc[idx] + b1[idx & 255], 0.f);
    }
}

// ---------------- GAT ----------------
template <int C>
__global__ void k_dots(const float* __restrict__ a_s, const float* __restrict__ a_d) {
    int gw = (blockIdx.x * blockDim.x + threadIdx.x) >> 5;
    int lane = threadIdx.x & 31;
    if (gw >= N_NODES) return;
    float s0 = 0.f, s1 = 0.f;
    const float* h = g_hg + (size_t)gw * C;
    #pragma unroll
    for (int j = lane; j < C; j += 32) {
        float v = h[j];
        s0 += v * __ldg(&a_s[j]);
        s1 += v * __ldg(&a_d[j]);
    }
    #pragma unroll
    for (int off = 16; off; off >>= 1) {
        s0 += __shfl_down_sync(0xffffffffu, s0, off);
        s1 += __shfl_down_sync(0xffffffffu, s1, off);
    }
    if (lane == 0) { g_as[gw] = s0; g_ad[gw] = s1; }
}
__global__ void k_gat_max(const int* __restrict__ ei) {
    int t = blockIdx.x * blockDim.x + threadIdx.x;
    if (t >= E_EDGES + N_NODES) return;
    int s, d;
    if (t < E_EDGES) { s = ei[t]; d = ei[E_EDGES + t]; } else { s = d = t - E_EDGES; }
    float x = lrelu02(g_as[s] + g_ad[d]);
    atomicMax(&g_mx[d], enc_key(x));
}
__global__ void k_gat_sum(const int* __restrict__ ei) {
    int t = blockIdx.x * blockDim.x + threadIdx.x;
    if (t >= E_EDGES + N_NODES) return;
    int s, d;
    if (t < E_EDGES) { s = ei[t]; d = ei[E_EDGES + t]; } else { s = d = t - E_EDGES; }
    float x = lrelu02(g_as[s] + g_ad[d]);
    atomicAdd(&g_sm[d], expf(x - dec_key(g_mx[d])));
}
template <int C>
__global__ void k_gat_scatter(const int* __restrict__ ei) {
    int gw = (blockIdx.x * blockDim.x + threadIdx.x) >> 5;
    int lane = threadIdx.x & 31;
    if (gw >= E_EDGES + N_NODES) return;
    int s, d;
    if (gw < E_EDGES) { s = ei[gw]; d = ei[E_EDGES + gw]; } else { s = d = gw - E_EDGES; }
    float x = lrelu02(g_as[s] + g_ad[d]);
    float w = expf(x - dec_key(g_mx[d])) / (g_sm[d] + 1e-16f);
    const float* hs = g_hg + (size_t)s * C;
    float* ac = g_acc + (size_t)d * C;
    #pragma unroll
    for (int j = 0; j < C / 32; j++)
        atomicAdd(&ac[lane + 32 * j], w * hs[lane + 32 * j]);
}
template <int C>
__global__ void k_gat_finish(const float* __restrict__ bias, float* __restrict__ dst) {
    int idx = blockIdx.x * blockDim.x + threadIdx.x;
    if (idx < N_NODES * C)
        dst[idx] = fmaxf(g_acc[idx] + bias[idx % C], 0.f);
}

// ---------------- decode MLP (warp per edge) ----------------
#define DEC_WARPS 8
__global__ __launch_bounds__(256)
void decode_kernel(const int* __restrict__ eli,
                   const float* __restrict__ Wm1, const float* __restrict__ bm1,
                   const float* __restrict__ Wm2, const float* __restrict__ bm2,
                   const float* __restrict__ Wm3, const float* __restrict__ bm3,
                   const float* __restrict__ Wm4, const float* __restrict__ bm4,
                   float* __restrict__ out) {
    __shared__ float sW1[128 * 64];
    __shared__ float es[DEC_WARPS][128];
    __shared__ float hs[DEC_WARPS][64];
    const int lane = threadIdx.x & 31;
    const int w = threadIdx.x >> 5;
    for (int i = threadIdx.x; i < 128 * 64; i += blockDim.x) sW1[i] = Wm1[i];
    __syncthreads();
    int gw = blockIdx.x * DEC_WARPS + w;
    int stride = gridDim.x * DEC_WARPS;
    for (int t = gw; t < L_EDGES; t += stride) {
        int s = eli[t], d = eli[L_EDGES + t];
        es[w][lane]      = g_z[(size_t)s * 64 + lane];
        es[w][lane + 32] = g_z[(size_t)s * 64 + lane + 32];
        es[w][lane + 64] = g_z[(size_t)d * 64 + lane];
        es[w][lane + 96] = g_z[(size_t)d * 64 + lane + 32];
        __syncwarp();
        // layer 1: 128 -> 64
        float a0 = __ldg(&bm1[lane]), a1 = __ldg(&bm1[lane + 32]);
        #pragma unroll 8
        for (int k = 0; k < 128; k++) {
            float ev = es[w][k];
            a0 = fmaf(ev, sW1[k * 64 + lane], a0);
            a1 = fmaf(ev, sW1[k * 64 + lane + 32], a1);
        }
        __syncwarp();
        hs[w][lane] = fmaxf(a0, 0.f); hs[w][lane + 32] = fmaxf(a1, 0.f);
        __syncwarp();
        // layer 2: 64 -> 64
        a0 = __ldg(&bm2[lane]); a1 = __ldg(&bm2[lane + 32]);
        #pragma unroll 8
        for (int k = 0; k < 64; k++) {
            float hv = hs[w][k];
            a0 = fmaf(hv, __ldg(&Wm2[k * 64 + lane]), a0);
            a1 = fmaf(hv, __ldg(&Wm2[k * 64 + lane + 32]), a1);
        }
        __syncwarp();
        hs[w][lane] = fmaxf(a0, 0.f); hs[w][lane + 32] = fmaxf(a1, 0.f);
        __syncwarp();
        // layer 3: 64 -> 64
        a0 = __ldg(&bm3[lane]); a1 = __ldg(&bm3[lane + 32]);
        #pragma unroll 8
        for (int k = 0; k < 64; k++) {
            float hv = hs[w][k];
            a0 = fmaf(hv, __ldg(&Wm3[k * 64 + lane]), a0);
            a1 = fmaf(hv, __ldg(&Wm3[k * 64 + lane + 32]), a1);
        }
        __syncwarp();
        hs[w][lane] = fmaxf(a0, 0.f); hs[w][lane + 32] = fmaxf(a1, 0.f);
        __syncwarp();
        // layer 4: 64 -> 3 (warp reduce)
        float o0 = 0.f, o1 = 0.f, o2 = 0.f;
        #pragma unroll
        for (int k = lane; k < 64; k += 32) {
            float hv = hs[w][k];
            o0 = fmaf(hv, __ldg(&Wm4[k * 3 + 0]), o0);
            o1 = fmaf(hv, __ldg(&Wm4[k * 3 + 1]), o1);
            o2 = fmaf(hv, __ldg(&Wm4[k * 3 + 2]), o2);
        }
        #pragma unroll
        for (int off = 16; off; off >>= 1) {
            o0 += __shfl_down_sync(0xffffffffu, o0, off);
            o1 += __shfl_down_sync(0xffffffffu, o1, off);
            o2 += __shfl_down_sync(0xffffffffu, o2, off);
        }
        if (lane == 0) {
            o0 += __ldg(&bm4[0]); o1 += __ldg(&bm4[1]); o2 += __ldg(&bm4[2]);
            int   idx  = 0;
            float best = o0;
            if (o1 > best) { best = o1; idx = 1; }
            if (o2 > best) { best = o2; idx = 2; }
            out[t]            = (float)idx;
            out[L_EDGES + t]  = best;
            out[2 * L_EDGES + t * 3 + 0] = o0;
            out[2 * L_EDGES + t * 3 + 1] = o1;
            out[2 * L_EDGES + t * 3 + 2] = o2;
        }
        __syncwarp();
    }
}

// ---------------- host launch ----------------
static inline int cdiv(int a, int b) { return (a + b - 1) / b; }

extern "C" void kernel_launch(void* const* d_in, const int* in_sizes, int n_in,
                              void* d_out, int out_size) {
    const float* x    = (const float*)d_in[0];
    const int*   ei   = (const int*)d_in[1];
    const int*   hn   = (const int*)d_in[2];
    const int*   he   = (const int*)d_in[3];
    const int*   eli  = (const int*)d_in[4];
    const float* W1   = (const float*)d_in[5];
    const float* b1   = (const float*)d_in[6];
    const float* W2   = (const float*)d_in[7];
    const float* a2s  = (const float*)d_in[8];
    const float* a2d  = (const float*)d_in[9];
    const float* b2   = (const float*)d_in[10];
    const float* W3   = (const float*)d_in[11];
    const float* a3s  = (const float*)d_in[12];
    const float* a3d  = (const float*)d_in[13];
    const float* b3   = (const float*)d_in[14];
    const float* Wm1  = (const float*)d_in[15];
    const float* bm1  = (const float*)d_in[16];
    const float* Wm2  = (const float*)d_in[17];
    const float* bm2  = (const float*)d_in[18];
    const float* Wm3  = (const float*)d_in[19];
    const float* bm3  = (const float*)d_in[20];
    const float* Wm4  = (const float*)d_in[21];
    const float* bm4  = (const float*)d_in[22];
    float* out = (float*)d_out;

    void *p_m, *p_acc, *p_D, *p_B, *p_mx, *p_sm, *p_h0, *p_h1, *p_hg, *p_z;
    cudaGetSymbolAddress(&p_m,   g_m);
    cudaGetSymbolAddress(&p_acc, g_acc);
    cudaGetSymbolAddress(&p_D,   g_D);
    cudaGetSymbolAddress(&p_B,   g_B);
    cudaGetSymbolAddress(&p_mx,  g_mx);
    cudaGetSymbolAddress(&p_sm,  g_sm);
    cudaGetSymbolAddress(&p_h0,  g_h0);
    cudaGetSymbolAddress(&p_h1,  g_h1);
    cudaGetSymbolAddress(&p_hg,  g_hg);
    cudaGetSymbolAddress(&p_z,   g_z);

    const int TB = 256;
    const int E2 = E_EDGES + N_NODES;  // edges + self loops

    // ===== hypergraph conv =====
    cudaMemsetAsync(p_D,   0, sizeof(float) * N_NODES, 0);
    cudaMemsetAsync(p_B,   0, sizeof(float) * N_HE, 0);
    cudaMemsetAsync(p_m,   0, sizeof(float) * N_HE * 256, 0);
    cudaMemsetAsync(p_acc, 0, sizeof(float) * N_NODES * 256, 0);
    k_count<<<cdiv(N_PAIRS, TB), TB>>>(hn, he);
    sgemm_k<<<dim3(256 / BN, cdiv(N_NODES, BM)), TB>>>(x, W1, (float*)p_h0, N_NODES, 256, 128);
    k_hc_scatter_m<<<cdiv(N_PAIRS * 32, TB), TB>>>(hn, he);
    k_scale_m<<<cdiv(N_HE * 256, TB), TB>>>();
    k_hc_scatter_n<<<cdiv(N_PAIRS * 32, TB), TB>>>(hn, he);
    k_hc_finish<<<cdiv(N_NODES * 256, TB), TB>>>(b1);

    // ===== GAT layer 1 (256 -> 256) =====
    sgemm_k<<<dim3(256 / BN, cdiv(N_NODES, BM)), TB>>>((float*)p_h1, W2, (float*)p_hg, N_NODES, 256, 256);
    k_dots<256><<<cdiv(N_NODES * 32, TB), TB>>>(a2s, a2d);
    cudaMemsetAsync(p_mx,  0, sizeof(unsigned) * N_NODES, 0);
    cudaMemsetAsync(p_sm,  0, sizeof(float) * N_NODES, 0);
    cudaMemsetAsync(p_acc, 0, sizeof(float) * N_NODES * 256, 0);
    k_gat_max<<<cdiv(E2, TB), TB>>>(ei);
    k_gat_sum<<<cdiv(E2, TB), TB>>>(ei);
    k_gat_scatter<256><<<cdiv(E2 * 32, TB), TB>>>(ei);
    k_gat_finish<256><<<cdiv(N_NODES * 256, TB), TB>>>(b2, (float*)p_h1);

    // ===== GAT layer 2 (256 -> 64) =====
    sgemm_k<<<dim3(64 / BN, cdiv(N_NODES, BM)), TB>>>((float*)p_h1, W3, (float*)p_hg, N_NODES, 64, 256);
    k_dots<64><<<cdiv(N_NODES * 32, TB), TB>>>(a3s, a3d);
    cudaMemsetAsync(p_mx,  0, sizeof(unsigned) * N_NODES, 0);
    cudaMemsetAsync(p_sm,  0, sizeof(float) * N_NODES, 0);
    cudaMemsetAsync(p_acc, 0, sizeof(float) * N_NODES * 64, 0);
    k_gat_max<<<cdiv(E2, TB), TB>>>(ei);
    k_gat_sum<<<cdiv(E2, TB), TB>>>(ei);
    k_gat_scatter<64><<<cdiv(E2 * 32, TB), TB>>>(ei);
    k_gat_finish<64><<<cdiv(N_NODES * 64, TB), TB>>>(b3, (float*)p_z);

    // ===== decode MLP =====
    decode_kernel<<<740, TB>>>(eli, Wm1, bm1, Wm2, bm2, Wm3, bm3, Wm4, bm4, out);
}

// round 2
// speedup vs baseline: 1.5922x; 1.5922x over previous
#include <cuda_runtime.h>
#include <math.h>

#define N_NODES   50000
#define N_HE      20000
#define N_PAIRS   400000
#define E_EDGES   800000
#define E2        (E_EDGES + N_NODES)
#define L_EDGES   100000

// ---------------- scratch (device globals; no runtime allocation) ----------------
__device__ float g_h0[N_NODES * 256];   // x @ W1
__device__ float g_m [N_HE    * 256];   // hyperedge messages
__device__ float g_h1[N_NODES * 256];   // activations (reused across layers)
__device__ float g_hg[N_NODES * 256];   // GEMM output features
__device__ float g_as[N_NODES];
__device__ float g_ad[N_NODES];
__device__ float g_z [N_NODES * 64];

// CSR structures
__device__ int c_cnt_he[N_HE],    c_off_he[N_HE],    c_cur_he[N_HE],    c_val_he[N_PAIRS];
__device__ int c_cnt_nd[N_NODES], c_off_nd[N_NODES], c_cur_nd[N_NODES], c_val_nd[N_PAIRS];
__device__ int c_cnt_g [N_NODES], c_off_g [N_NODES], c_cur_g [N_NODES], c_val_g [E2];

__device__ __forceinline__ float lrelu02(float x) { return x > 0.f ? x : 0.2f * x; }

// ---------------- GEMM: C[M,N] = A[M,K] @ B[K,N], row-major fp32 ----------------
template<int BM, int BN, int BK, int TM, int TN>
__global__ void __launch_bounds__((BM / TM) * (BN / TN))
sgemm(const float* __restrict__ A, const float* __restrict__ B, float* __restrict__ C,
      int M, int N, int K) {
    constexpr int NT = (BM / TM) * (BN / TN);
    __shared__ float As[BK][BM + 4];
    __shared__ float Bs[BK][BN];
    const int tid = threadIdx.x;
    const int tx = tid % (BN / TN);
    const int ty = tid / (BN / TN);
    const int rowBase = blockIdx.y * BM, colBase = blockIdx.x * BN;
    float acc[TM][TN] = {};
    for (int k0 = 0; k0 < K; k0 += BK) {
        #pragma unroll
        for (int i = tid; i < BM * BK / 4; i += NT) {
            int r = (i * 4) / BK, c = (i * 4) % BK;
            int gr = rowBase + r;
            float4 v = (gr < M) ? *(const float4*)&A[(size_t)gr * K + k0 + c]
                                : make_float4(0.f, 0.f, 0.f, 0.f);
            As[c + 0][r] = v.x; As[c + 1][r] = v.y; As[c + 2][r] = v.z; As[c + 3][r] = v.w;
        }
        #pragma unroll
        for (int i = tid; i < BK * BN / 4; i += NT) {
            int r = (i * 4) / BN, c = (i * 4) % BN;
            *(float4*)&Bs[r][c] = *(const float4*)&B[(size_t)(k0 + r) * N + colBase + c];
        }
        __syncthreads();
        #pragma unroll
        for (int k = 0; k < BK; k++) {
            float a[TM], b[TN];
            #pragma unroll
            for (int i = 0; i < TM; i++) a[i] = As[k][ty * TM + i];
            #pragma unroll
            for (int j = 0; j < TN; j++) b[j] = Bs[k][tx * TN + j];
            #pragma unroll
            for (int i = 0; i < TM; i++)
                #pragma unroll
                for (int j = 0; j < TN; j++) acc[i][j] = fmaf(a[i], b[j], acc[i][j]);
        }
        __syncthreads();
    }
    #pragma unroll
    for (int i = 0; i < TM; i++) {
        int gr = rowBase + ty * TM + i;
        if (gr < M) {
            #pragma unroll
            for (int j = 0; j < TN; j += 4)
                *(float4*)&C[(size_t)gr * N + colBase + tx * TN + j] =
                    make_float4(acc[i][j], acc[i][j + 1], acc[i][j + 2], acc[i][j + 3]);
        }
    }
}

// ---------------- CSR build ----------------
__global__ void k_cnt_hc(const int* __restrict__ hn, const int* __restrict__ he) {
    int i = blockIdx.x * blockDim.x + threadIdx.x;
    if (i < N_PAIRS) {
        atomicAdd(&c_cnt_nd[hn[i]], 1);
        atomicAdd(&c_cnt_he[he[i]], 1);
    }
}
__global__ void k_cnt_gat(const int* __restrict__ ei) {
    int t = blockIdx.x * blockDim.x + threadIdx.x;
    if (t >= E2) return;
    int d = (t < E_EDGES) ? ei[E_EDGES + t] : (t - E_EDGES);
    atomicAdd(&c_cnt_g[d], 1);
}
// single-block exclusive scan (warp-shuffle based)
__global__ void __launch_bounds__(1024)
k_scan(const int* __restrict__ in, int* __restrict__ off, int* __restrict__ cur, int n) {
    const int t = threadIdx.x;
    __shared__ int wsum[32];
    __shared__ int run_s;
    if (t == 0) run_s = 0;
    __syncthreads();
    for (int base = 0; base < n; base += 1024) {
        int v = (base + t < n) ? in[base + t] : 0;
        int x = v;
        #pragma unroll
        for (int o = 1; o < 32; o <<= 1) {
            int y = __shfl_up_sync(0xffffffffu, x, o);
            if ((t & 31) >= o) x += y;
        }
        if ((t & 31) == 31) wsum[t >> 5] = x;
        __syncthreads();
        if (t < 32) {
            int y = wsum[t], z = y;
            #pragma unroll
            for (int o = 1; o < 32; o <<= 1) {
                int u = __shfl_up_sync(0xffffffffu, z, o);
                if (t >= o) z += u;
            }
            wsum[t] = z - y;  // exclusive warp offset
        }
        __syncthreads();
        int incl = x + wsum[t >> 5];
        int excl = incl - v + run_s;
        if (base + t < n) { off[base + t] = excl; cur[base + t] = excl; }
        __syncthreads();
        if (t == 1023) run_s += incl;
        __syncthreads();
    }
}
__global__ void k_fill_hc(const int* __restrict__ hn, const int* __restrict__ he) {
    int i = blockIdx.x * blockDim.x + threadIdx.x;
    if (i < N_PAIRS) {
        int n = hn[i], e = he[i];
        c_val_he[atomicAdd(&c_cur_he[e], 1)] = n;
        c_val_nd[atomicAdd(&c_cur_nd[n], 1)] = e;
    }
}
__global__ void k_fill_gat(const int* __restrict__ ei) {
    int t = blockIdx.x * blockDim.x + threadIdx.x;
    if (t >= E2) return;
    int s, d;
    if (t < E_EDGES) { s = ei[t]; d = ei[E_EDGES + t]; } else { s = d = t - E_EDGES; }
    c_val_g[atomicAdd(&c_cur_g[d], 1)] = s;
}

// ---------------- hypergraph conv (gather) ----------------
// m[e] = (1/B[e]) * sum_{n in e} h0[n]
__global__ void k_hc_edge_gather() {
    int gw = (blockIdx.x * blockDim.x + threadIdx.x) >> 5;
    int lane = threadIdx.x & 31;
    if (gw >= N_HE) return;
    int deg = c_cnt_he[gw], start = c_off_he[gw];
    float acc[8] = {};
    for (int i = 0; i < deg; i++) {
        const float* src = g_h0 + (size_t)c_val_he[start + i] * 256;
        #pragma unroll
        for (int j = 0; j < 8; j++) acc[j] += src[lane + 32 * j];
    }
    float binv = deg > 0 ? 1.f / (float)deg : 0.f;
    float* dst = g_m + (size_t)gw * 256;
    #pragma unroll
    for (int j = 0; j < 8; j++) dst[lane + 32 * j] = acc[j] * binv;
}
// h1[n] = relu((1/D[n]) * sum_{e ∋ n} m[e] + b1)
__global__ void k_hc_node_gather(const float* __restrict__ b1) {
    int gw = (blockIdx.x * blockDim.x + threadIdx.x) >> 5;
    int lane = threadIdx.x & 31;
    if (gw >= N_NODES) return;
    int deg = c_cnt_nd[gw], start = c_off_nd[gw];
    float acc[8] = {};
    for (int i = 0; i < deg; i++) {
        const float* src = g_m + (size_t)c_val_nd[start + i] * 256;
        #pragma unroll
        for (int j = 0; j < 8; j++) acc[j] += src[lane + 32 * j];
    }
    float dinv = deg > 0 ? 1.f / (float)deg : 0.f;
    float* dst = g_h1 + (size_t)gw * 256;
    #pragma unroll
    for (int j = 0; j < 8; j++)
        dst[lane + 32 * j] = fmaxf(acc[j] * dinv + __ldg(&b1[lane + 32 * j]), 0.f);
}

// ---------------- GAT ----------------
template <int C>
__global__ void k_dots(const float* __restrict__ a_s, const float* __restrict__ a_d) {
    int gw = (blockIdx.x * blockDim.x + threadIdx.x) >> 5;
    int lane = threadIdx.x & 31;
    if (gw >= N_NODES) return;
    float s0 = 0.f, s1 = 0.f;
    const float* h = g_hg + (size_t)gw * C;
    #pragma unroll
    for (int j = lane; j < C; j += 32) {
        float v = h[j];
        s0 += v * __ldg(&a_s[j]);
        s1 += v * __ldg(&a_d[j]);
    }
    #pragma unroll
    for (int off = 16; off; off >>= 1) {
        s0 += __shfl_down_sync(0xffffffffu, s0, off);
        s1 += __shfl_down_sync(0xffffffffu, s1, off);
    }
    if (lane == 0) { g_as[gw] = s0; g_ad[gw] = s1; }
}
// warp per dst node: local softmax over incoming edges + weighted gather + bias + relu
template <int C>
__global__ void k_gat_aggr(const float* __restrict__ bias, float* __restrict__ dst) {
    int gw = (blockIdx.x * blockDim.x + threadIdx.x) >> 5;
    int lane = threadIdx.x & 31;
    if (gw >= N_NODES) return;
    int deg = c_cnt_g[gw], start = c_off_g[gw];
    float adst = g_ad[gw];
    // pass 1: max
    float mx = -1e30f;
    for (int i = lane; i < deg; i += 32)
        mx = fmaxf(mx, lrelu02(g_as[c_val_g[start + i]] + adst));
    #pragma unroll
    for (int off = 16; off; off >>= 1)
        mx = fmaxf(mx, __shfl_xor_sync(0xffffffffu, mx, off));
    // pass 2: sum of exp
    float sm = 0.f;
    for (int i = lane; i < deg; i += 32)
        sm += expf(lrelu02(g_as[c_val_g[start + i]] + adst) - mx);
    #pragma unroll
    for (int off = 16; off; off >>= 1)
        sm += __shfl_xor_sync(0xffffffffu, sm, off);
    float inv = 1.f / (sm + 1e-16f);
    // pass 3: weighted gather
    float acc[C / 32] = {};
    for (int i = 0; i < deg; i++) {
        int s = c_val_g[start + i];
        float w = expf(lrelu02(g_as[s] + adst) - mx) * inv;
        const float* hs = g_hg + (size_t)s * C;
        #pragma unroll
        for (int j = 0; j < C / 32; j++) acc[j] = fmaf(w, hs[lane + 32 * j], acc[j]);
    }
    float* o = dst + (size_t)gw * C;
    #pragma unroll
    for (int j = 0; j < C / 32; j++)
        o[lane + 32 * j] = fmaxf(acc[j] + __ldg(&bias[lane + 32 * j]), 0.f);
}

// ---------------- decode MLP (warp per edge) ----------------
#define DEC_WARPS 8
__global__ __launch_bounds__(256)
void decode_kernel(const int* __restrict__ eli,
                   const float* __restrict__ Wm1, const float* __restrict__ bm1,
                   const float* __restrict__ Wm2, const float* __restrict__ bm2,
                   const float* __restrict__ Wm3, const float* __restrict__ bm3,
                   const float* __restrict__ Wm4, const float* __restrict__ bm4,
                   float* __restrict__ out) {
    __shared__ float sW1[128 * 64];
    __shared__ float es[DEC_WARPS][128];
    __shared__ float hs[DEC_WARPS][64];
    const int lane = threadIdx.x & 31;
    const int w = threadIdx.x >> 5;
    for (int i = threadIdx.x; i < 128 * 64; i += blockDim.x) sW1[i] = Wm1[i];
    __syncthreads();
    int gw = blockIdx.x * DEC_WARPS + w;
    int stride = gridDim.x * DEC_WARPS;
    for (int t = gw; t < L_EDGES; t += stride) {
        int s = eli[t], d = eli[L_EDGES + t];
        es[w][lane]      = g_z[(size_t)s * 64 + lane];
        es[w][lane + 32] = g_z[(size_t)s * 64 + lane + 32];
        es[w][lane + 64] = g_z[(size_t)d * 64 + lane];
        es[w][lane + 96] = g_z[(size_t)d * 64 + lane + 32];
        __syncwarp();
        float a0 = __ldg(&bm1[lane]), a1 = __ldg(&bm1[lane + 32]);
        #pragma unroll 8
        for (int k = 0; k < 128; k++) {
            float ev = es[w][k];
            a0 = fmaf(ev, sW1[k * 64 + lane], a0);
            a1 = fmaf(ev, sW1[k * 64 + lane + 32], a1);
        }
        __syncwarp();
        hs[w][lane] = fmaxf(a0, 0.f); hs[w][lane + 32] = fmaxf(a1, 0.f);
        __syncwarp();
        a0 = __ldg(&bm2[lane]); a1 = __ldg(&bm2[lane + 32]);
        #pragma unroll 8
        for (int k = 0; k < 64; k++) {
            float hv = hs[w][k];
            a0 = fmaf(hv, __ldg(&Wm2[k * 64 + lane]), a0);
            a1 = fmaf(hv, __ldg(&Wm2[k * 64 + lane + 32]), a1);
        }
        __syncwarp();
        hs[w][lane] = fmaxf(a0, 0.f); hs[w][lane + 32] = fmaxf(a1, 0.f);
        __syncwarp();
        a0 = __ldg(&bm3[lane]); a1 = __ldg(&bm3[lane + 32]);
        #pragma unroll 8
        for (int k = 0; k < 64; k++) {
            float hv = hs[w][k];
            a0 = fmaf(hv, __ldg(&Wm3[k * 64 + lane]), a0);
            a1 = fmaf(hv, __ldg(&Wm3[k * 64 + lane + 32]), a1);
        }
        __syncwarp();
        hs[w][lane] = fmaxf(a0, 0.f); hs[w][lane + 32] = fmaxf(a1, 0.f);
        __syncwarp();
        float o0 = 0.f, o1 = 0.f, o2 = 0.f;
        #pragma unroll
        for (int k = lane; k < 64; k += 32) {
            float hv = hs[w][k];
            o0 = fmaf(hv, __ldg(&Wm4[k * 3 + 0]), o0);
            o1 = fmaf(hv, __ldg(&Wm4[k * 3 + 1]), o1);
            o2 = fmaf(hv, __ldg(&Wm4[k * 3 + 2]), o2);
        }
        #pragma unroll
        for (int off = 16; off; off >>= 1) {
            o0 += __shfl_down_sync(0xffffffffu, o0, off);
            o1 += __shfl_down_sync(0xffffffffu, o1, off);
            o2 += __shfl_down_sync(0xffffffffu, o2, off);
        }
        if (lane == 0) {
            o0 += __ldg(&bm4[0]); o1 += __ldg(&bm4[1]); o2 += __ldg(&bm4[2]);
            int   idx  = 0;
            float best = o0;
            if (o1 > best) { best = o1; idx = 1; }
            if (o2 > best) { best = o2; idx = 2; }
            out[t]           = (float)idx;
            out[L_EDGES + t] = best;
            out[2 * L_EDGES + t * 3 + 0] = o0;
            out[2 * L_EDGES + t * 3 + 1] = o1;
            out[2 * L_EDGES + t * 3 + 2] = o2;
        }
        __syncwarp();
    }
}

// ---------------- host launch ----------------
static inline int cdiv(int a, int b) { return (a + b - 1) / b; }

extern "C" void kernel_launch(void* const* d_in, const int* in_sizes, int n_in,
                              void* d_out, int out_size) {
    const float* x   = (const float*)d_in[0];
    const int*   ei  = (const int*)d_in[1];
    const int*   hn  = (const int*)d_in[2];
    const int*   he  = (const int*)d_in[3];
    const int*   eli = (const int*)d_in[4];
    const float* W1  = (const float*)d_in[5];
    const float* b1  = (const float*)d_in[6];
    const float* W2  = (const float*)d_in[7];
    const float* a2s = (const float*)d_in[8];
    const float* a2d = (const float*)d_in[9];
    const float* b2  = (const float*)d_in[10];
    const float* W3  = (const float*)d_in[11];
    const float* a3s = (const float*)d_in[12];
    const float* a3d = (const float*)d_in[13];
    const float* b3  = (const float*)d_in[14];
    const float* Wm1 = (const float*)d_in[15];
    const float* bm1 = (const float*)d_in[16];
    const float* Wm2 = (const float*)d_in[17];
    const float* bm2 = (const float*)d_in[18];
    const float* Wm3 = (const float*)d_in[19];
    const float* bm3 = (const float*)d_in[20];
    const float* Wm4 = (const float*)d_in[21];
    const float* bm4 = (const float*)d_in[22];
    float* out = (float*)d_out;

    void *p_cnt_he, *p_off_he, *p_cur_he, *p_cnt_nd, *p_off_nd, *p_cur_nd;
    void *p_cnt_g, *p_off_g, *p_cur_g;
    void *p_h0, *p_h1, *p_hg, *p_z;
    cudaGetSymbolAddress(&p_cnt_he, c_cnt_he);
    cudaGetSymbolAddress(&p_off_he, c_off_he);
    cudaGetSymbolAddress(&p_cur_he, c_cur_he);
    cudaGetSymbolAddress(&p_cnt_nd, c_cnt_nd);
    cudaGetSymbolAddress(&p_off_nd, c_off_nd);
    cudaGetSymbolAddress(&p_cur_nd, c_cur_nd);
    cudaGetSymbolAddress(&p_cnt_g,  c_cnt_g);
    cudaGetSymbolAddress(&p_off_g,  c_off_g);
    cudaGetSymbolAddress(&p_cur_g,  c_cur_g);
    cudaGetSymbolAddress(&p_h0, g_h0);
    cudaGetSymbolAddress(&p_h1, g_h1);
    cudaGetSymbolAddress(&p_hg, g_hg);
    cudaGetSymbolAddress(&p_z,  g_z);

    const int TB = 256;

    // ===== CSR builds =====
    cudaMemsetAsync(p_cnt_he, 0, sizeof(int) * N_HE, 0);
    cudaMemsetAsync(p_cnt_nd, 0, sizeof(int) * N_NODES, 0);
    cudaMemsetAsync(p_cnt_g,  0, sizeof(int) * N_NODES, 0);
    k_cnt_hc<<<cdiv(N_PAIRS, TB), TB>>>(hn, he);
    k_cnt_gat<<<cdiv(E2, TB), TB>>>(ei);
    k_scan<<<1, 1024>>>((int*)p_cnt_he, (int*)p_off_he, (int*)p_cur_he, N_HE);
    k_scan<<<1, 1024>>>((int*)p_cnt_nd, (int*)p_off_nd, (int*)p_cur_nd, N_NODES);
    k_scan<<<1, 1024>>>((int*)p_cnt_g,  (int*)p_off_g,  (int*)p_cur_g,  N_NODES);
    k_fill_hc<<<cdiv(N_PAIRS, TB), TB>>>(hn, he);
    k_fill_gat<<<cdiv(E2, TB), TB>>>(ei);

    // ===== hypergraph conv =====
    sgemm<128, 128, 8, 8, 8><<<dim3(2, cdiv(N_NODES, 128)), 256>>>(x, W1, (float*)p_h0, N_NODES, 256, 128);
    k_hc_edge_gather<<<cdiv(N_HE * 32, TB), TB>>>();
    k_hc_node_gather<<<cdiv(N_NODES * 32, TB), TB>>>(b1);

    // ===== GAT layer 1 (256 -> 256) =====
    sgemm<128, 128, 8, 8, 8><<<dim3(2, cdiv(N_NODES, 128)), 256>>>((float*)p_h1, W2, (float*)p_hg, N_NODES, 256, 256);
    k_dots<256><<<cdiv(N_NODES * 32, TB), TB>>>(a2s, a2d);
    k_gat_aggr<256><<<cdiv(N_NODES * 32, TB), TB>>>(b2, (float*)p_h1);

    // ===== GAT layer 2 (256 -> 64) =====
    sgemm<128, 64, 8, 8, 4><<<dim3(1, cdiv(N_NODES, 128)), 256>>>((float*)p_h1, W3, (float*)p_hg, N_NODES, 64, 256);
    k_dots<64><<<cdiv(N_NODES * 32, TB), TB>>>(a3s, a3d);
    k_gat_aggr<64><<<cdiv(N_NODES * 32, TB), TB>>>(b3, (float*)p_z);

    // ===== decode MLP =====
    decode_kernel<<<740, TB>>>(eli, Wm1, bm1, Wm2, bm2, Wm3, bm3, Wm4, bm4, out);
}

// round 3
// speedup vs baseline: 1.5965x; 1.0027x over previous
#include <cuda_runtime.h>
#include <math.h>

#define N_NODES   50000
#define N_HE      20000
#define N_PAIRS   400000
#define E_EDGES   800000
#define E2        (E_EDGES + N_NODES)
#define L_EDGES   100000

// ---------------- scratch (device globals; no runtime allocation) ----------------
__device__ float g_h0[N_NODES * 256];   // x @ W1
__device__ float g_m [N_HE    * 256];   // hyperedge messages
__device__ float g_h1[N_NODES * 256];   // activations (reused across layers)
__device__ float g_hg[N_NODES * 256];   // GEMM output features
__device__ float g_as[N_NODES];
__device__ float g_ad[N_NODES];
__device__ float g_z [N_NODES * 64];

// CSR structures
__device__ int c_cnt_he[N_HE],    c_off_he[N_HE],    c_cur_he[N_HE],    c_val_he[N_PAIRS];
__device__ int c_cnt_nd[N_NODES], c_off_nd[N_NODES], c_cur_nd[N_NODES], c_val_nd[N_PAIRS];
__device__ int c_cnt_g [N_NODES], c_off_g [N_NODES], c_cur_g [N_NODES], c_val_g [E2];

__device__ __forceinline__ float lrelu02(float x) { return x > 0.f ? x : 0.2f * x; }
__device__ __forceinline__ void f4add(float4& a, const float4 b) {
    a.x += b.x; a.y += b.y; a.z += b.z; a.w += b.w;
}
__device__ __forceinline__ void f4fma(float4& a, float w, const float4 b) {
    a.x = fmaf(w, b.x, a.x); a.y = fmaf(w, b.y, a.y);
    a.z = fmaf(w, b.z, a.z); a.w = fmaf(w, b.w, a.w);
}

// ---------------- GEMM: C[M,N] = A[M,K] @ B[K,N], row-major fp32, double-buffered ----
template<int BM, int BN, int BK, int TM, int TN>
__global__ void __launch_bounds__((BM / TM) * (BN / TN))
sgemm(const float* __restrict__ A, const float* __restrict__ B, float* __restrict__ C,
      int M, int N, int K) {
    constexpr int NT = (BM / TM) * (BN / TN);
    constexpr int LA = BM * BK / 4 / NT;
    constexpr int LB = BK * BN / 4 / NT;
    __shared__ float As[2][BK][BM + 4];
    __shared__ float Bs[2][BK][BN];
    const int tid = threadIdx.x;
    const int tx = tid % (BN / TN);
    const int ty = tid / (BN / TN);
    const int rowBase = blockIdx.y * BM, colBase = blockIdx.x * BN;
    float4 ra[LA], rb[LB];

    auto loadA = [&](int k0) {
        #pragma unroll
        for (int s = 0; s < LA; s++) {
            int f = tid + s * NT;
            int r = f / (BK / 4), c = (f % (BK / 4)) * 4;
            int gr = rowBase + r;
            ra[s] = (gr < M) ? *(const float4*)&A[(size_t)gr * K + k0 + c]
                             : make_float4(0.f, 0.f, 0.f, 0.f);
        }
    };
    auto loadB = [&](int k0) {
        #pragma unroll
        for (int s = 0; s < LB; s++) {
            int f = tid + s * NT;
            int r = f / (BN / 4), c = (f % (BN / 4)) * 4;
            rb[s] = *(const float4*)&B[(size_t)(k0 + r) * N + colBase + c];
        }
    };
    auto stA = [&](int buf) {
        #pragma unroll
        for (int s = 0; s < LA; s++) {
            int f = tid + s * NT;
            int r = f / (BK / 4), c = (f % (BK / 4)) * 4;
            As[buf][c + 0][r] = ra[s].x; As[buf][c + 1][r] = ra[s].y;
            As[buf][c + 2][r] = ra[s].z; As[buf][c + 3][r] = ra[s].w;
        }
    };
    auto stB = [&](int buf) {
        #pragma unroll
        for (int s = 0; s < LB; s++) {
            int f = tid + s * NT;
            int r = f / (BN / 4), c = (f % (BN / 4)) * 4;
            *(float4*)&Bs[buf][r][c] = rb[s];
        }
    };

    float acc[TM][TN] = {};
    loadA(0); loadB(0); stA(0); stB(0);
    __syncthreads();
    const int T = K / BK;
    int cur = 0;
    for (int t = 0; t < T; t++) {
        if (t + 1 < T) { loadA((t + 1) * BK); loadB((t + 1) * BK); }
        #pragma unroll
        for (int k = 0; k < BK; k++) {
            float a[TM], b[TN];
            #pragma unroll
            for (int i = 0; i < TM; i++) a[i] = As[cur][k][ty * TM + i];
            #pragma unroll
            for (int j = 0; j < TN; j++) b[j] = Bs[cur][k][tx * TN + j];
            #pragma unroll
            for (int i = 0; i < TM; i++)
                #pragma unroll
                for (int j = 0; j < TN; j++) acc[i][j] = fmaf(a[i], b[j], acc[i][j]);
        }
        if (t + 1 < T) {
            stA(cur ^ 1); stB(cur ^ 1);
            __syncthreads();
            cur ^= 1;
        }
    }
    #pragma unroll
    for (int i = 0; i < TM; i++) {
        int gr = rowBase + ty * TM + i;
        if (gr < M) {
            #pragma unroll
            for (int j = 0; j < TN; j += 4)
                *(float4*)&C[(size_t)gr * N + colBase + tx * TN + j] =
                    make_float4(acc[i][j], acc[i][j + 1], acc[i][j + 2], acc[i][j + 3]);
        }
    }
}

// ---------------- CSR build ----------------
__global__ void k_cnt_all(const int* __restrict__ hn, const int* __restrict__ he,
                          const int* __restrict__ ei) {
    int i = blockIdx.x * blockDim.x + threadIdx.x;
    if (i < N_PAIRS) {
        atomicAdd(&c_cnt_nd[hn[i]], 1);
        atomicAdd(&c_cnt_he[he[i]], 1);
    }
    int t = i - N_PAIRS;
    if (t >= 0 && t < E2) {
        int d = (t < E_EDGES) ? ei[E_EDGES + t] : (t - E_EDGES);
        atomicAdd(&c_cnt_g[d], 1);
    }
}

// block-wide exclusive scan: 1024 threads x 8 elements/thread per iteration
__device__ void scan_block(const int* __restrict__ in, int* __restrict__ off,
                           int* __restrict__ cur, int n) {
    const int tid = threadIdx.x;
    const int lane = tid & 31, wid = tid >> 5;
    __shared__ int wsums[32];
    __shared__ int s_tot;
    int carry = 0;
    for (int base = 0; base < n; base += 8192) {
        int i0 = base + tid * 8;
        int o[8], v[8];
        #pragma unroll
        for (int j = 0; j < 8; j++) o[j] = (i0 + j < n) ? in[i0 + j] : 0;
        v[0] = o[0];
        #pragma unroll
        for (int j = 1; j < 8; j++) v[j] = v[j - 1] + o[j];
        int tsum = v[7];
        int x = tsum;
        #pragma unroll
        for (int d = 1; d < 32; d <<= 1) {
            int y = __shfl_up_sync(0xffffffffu, x, d);
            if (lane >= d) x += y;
        }
        if (lane == 31) wsums[wid] = x;
        __syncthreads();
        if (wid == 0) {
            int y = wsums[lane], z = y;
            #pragma unroll
            for (int d = 1; d < 32; d <<= 1) {
                int u = __shfl_up_sync(0xffffffffu, z, d);
                if (lane >= d) z += u;
            }
            if (lane == 31) s_tot = z;
            wsums[lane] = z - y;  // exclusive warp offsets
        }
        __syncthreads();
        int offv = carry + wsums[wid] + (x - tsum);
        #pragma unroll
        for (int j = 0; j < 8; j++) {
            if (i0 + j < n) {
                int e = offv + v[j] - o[j];
                off[i0 + j] = e;
                cur[i0 + j] = e;
            }
        }
        carry += s_tot;
        __syncthreads();
    }
}
__global__ void __launch_bounds__(1024) k_scan3() {
    if (blockIdx.x == 0)      scan_block(c_cnt_he, c_off_he, c_cur_he, N_HE);
    else if (blockIdx.x == 1) scan_block(c_cnt_nd, c_off_nd, c_cur_nd, N_NODES);
    else                      scan_block(c_cnt_g,  c_off_g,  c_cur_g,  N_NODES);
}

__global__ void k_fill_all(const int* __restrict__ hn, const int* __restrict__ he,
                           const int* __restrict__ ei) {
    int i = blockIdx.x * blockDim.x + threadIdx.x;
    if (i < N_PAIRS) {
        int n = hn[i], e = he[i];
        c_val_he[atomicAdd(&c_cur_he[e], 1)] = n;
        c_val_nd[atomicAdd(&c_cur_nd[n], 1)] = e;
    }
    int t = i - N_PAIRS;
    if (t >= 0 && t < E2) {
        int s, d;
        if (t < E_EDGES) { s = ei[t]; d = ei[E_EDGES + t]; } else { s = d = t - E_EDGES; }
        c_val_g[atomicAdd(&c_cur_g[d], 1)] = s;
    }
}

// ---------------- hypergraph conv (gather, float4) ----------------
__global__ void k_hc_edge_gather() {
    int gw = (blockIdx.x * blockDim.x + threadIdx.x) >> 5;
    int lane = threadIdx.x & 31;
    if (gw >= N_HE) return;
    int deg = c_cnt_he[gw], start = c_off_he[gw];
    float4 a0 = {0, 0, 0, 0}, a1 = {0, 0, 0, 0};
    for (int i = 0; i < deg; i++) {
        const float4* src = (const float4*)(g_h0 + (size_t)c_val_he[start + i] * 256);
        f4add(a0, src[lane]);
        f4add(a1, src[lane + 32]);
    }
    float binv = deg > 0 ? 1.f / (float)deg : 0.f;
    a0.x *= binv; a0.y *= binv; a0.z *= binv; a0.w *= binv;
    a1.x *= binv; a1.y *= binv; a1.z *= binv; a1.w *= binv;
    float4* dst = (float4*)(g_m + (size_t)gw * 256);
    dst[lane] = a0;
    dst[lane + 32] = a1;
}
__global__ void k_hc_node_gather(const float* __restrict__ b1) {
    int gw = (blockIdx.x * blockDim.x + threadIdx.x) >> 5;
    int lane = threadIdx.x & 31;
    if (gw >= N_NODES) return;
    int deg = c_cnt_nd[gw], start = c_off_nd[gw];
    float4 a0 = {0, 0, 0, 0}, a1 = {0, 0, 0, 0};
    for (int i = 0; i < deg; i++) {
        const float4* src = (const float4*)(g_m + (size_t)c_val_nd[start + i] * 256);
        f4add(a0, src[lane]);
        f4add(a1, src[lane + 32]);
    }
    float dinv = deg > 0 ? 1.f / (float)deg : 0.f;
    float4 bb0 = __ldg((const float4*)b1 + lane);
    float4 bb1 = __ldg((const float4*)b1 + lane + 32);
    float4 r0, r1;
    r0.x = fmaxf(a0.x * dinv + bb0.x, 0.f); r0.y = fmaxf(a0.y * dinv + bb0.y, 0.f);
    r0.z = fmaxf(a0.z * dinv + bb0.z, 0.f); r0.w = fmaxf(a0.w * dinv + bb0.w, 0.f);
    r1.x = fmaxf(a1.x * dinv + bb1.x, 0.f); r1.y = fmaxf(a1.y * dinv + bb1.y, 0.f);
    r1.z = fmaxf(a1.z * dinv + bb1.z, 0.f); r1.w = fmaxf(a1.w * dinv + bb1.w, 0.f);
    float4* dst = (float4*)(g_h1 + (size_t)gw * 256);
    dst[lane] = r0;
    dst[lane + 32] = r1;
}

// ---------------- GAT ----------------
template <int C>
__global__ void k_dots(const float* __restrict__ a_s, const float* __restrict__ a_d) {
    int gw = (blockIdx.x * blockDim.x + threadIdx.x) >> 5;
    int lane = threadIdx.x & 31;
    if (gw >= N_NODES) return;
    float s0 = 0.f, s1 = 0.f;
    const float4* h = (const float4*)(g_hg + (size_t)gw * C);
    #pragma unroll
    for (int j = lane; j < C / 4; j += 32) {
        float4 v = h[j];
        float4 as4 = __ldg((const float4*)a_s + j);
        float4 ad4 = __ldg((const float4*)a_d + j);
        s0 += v.x * as4.x + v.y * as4.y + v.z * as4.z + v.w * as4.w;
        s1 += v.x * ad4.x + v.y * ad4.y + v.z * ad4.z + v.w * ad4.w;
    }
    #pragma unroll
    for (int off = 16; off; off >>= 1) {
        s0 += __shfl_down_sync(0xffffffffu, s0, off);
        s1 += __shfl_down_sync(0xffffffffu, s1, off);
    }
    if (lane == 0) { g_as[gw] = s0; g_ad[gw] = s1; }
}
// warp per dst node: local softmax + weighted gather + bias + relu
template <int C>
__global__ void k_gat_aggr(const float* __restrict__ bias, float* __restrict__ dst) {
    int gw = (blockIdx.x * blockDim.x + threadIdx.x) >> 5;
    int lane = threadIdx.x & 31;
    if (gw >= N_NODES) return;
    int deg = c_cnt_g[gw], start = c_off_g[gw];
    float adst = g_ad[gw];
    float mx = -1e30f;
    for (int i = lane; i < deg; i += 32)
        mx = fmaxf(mx, lrelu02(g_as[c_val_g[start + i]] + adst));
    #pragma unroll
    for (int off = 16; off; off >>= 1)
        mx = fmaxf(mx, __shfl_xor_sync(0xffffffffu, mx, off));
    float sm = 0.f;
    for (int i = lane; i < deg; i += 32)
        sm += expf(lrelu02(g_as[c_val_g[start + i]] + adst) - mx);
    #pragma unroll
    for (int off = 16; off; off >>= 1)
        sm += __shfl_xor_sync(0xffffffffu, sm, off);
    float inv = 1.f / (sm + 1e-16f);
    if constexpr (C == 256) {
        float4 a0 = {0, 0, 0, 0}, a1 = {0, 0, 0, 0};
        for (int i = 0; i < deg; i++) {
            int s = c_val_g[start + i];
            float w = expf(lrelu02(g_as[s] + adst) - mx) * inv;
            const float4* hs = (const float4*)(g_hg + (size_t)s * 256);
            f4fma(a0, w, hs[lane]);
            f4fma(a1, w, hs[lane + 32]);
        }
        float4 bb0 = __ldg((const float4*)bias + lane);
        float4 bb1 = __ldg((const float4*)bias + lane + 32);
        float4 r0, r1;
        r0.x = fmaxf(a0.x + bb0.x, 0.f); r0.y = fmaxf(a0.y + bb0.y, 0.f);
        r0.z = fmaxf(a0.z + bb0.z, 0.f); r0.w = fmaxf(a0.w + bb0.w, 0.f);
        r1.x = fmaxf(a1.x + bb1.x, 0.f); r1.y = fmaxf(a1.y + bb1.y, 0.f);
        r1.z = fmaxf(a1.z + bb1.z, 0.f); r1.w = fmaxf(a1.w + bb1.w, 0.f);
        float4* o = (float4*)(dst + (size_t)gw * 256);
        o[lane] = r0;
        o[lane + 32] = r1;
    } else {
        float acc[C / 32] = {};
        for (int i = 0; i < deg; i++) {
            int s = c_val_g[start + i];
            float w = expf(lrelu02(g_as[s] + adst) - mx) * inv;
            const float* hs = g_hg + (size_t)s * C;
            #pragma unroll
            for (int j = 0; j < C / 32; j++) acc[j] = fmaf(w, hs[lane + 32 * j], acc[j]);
        }
        float* o = dst + (size_t)gw * C;
        #pragma unroll
        for (int j = 0; j < C / 32; j++)
            o[lane + 32 * j] = fmaxf(acc[j] + __ldg(&bias[lane + 32 * j]), 0.f);
    }
}

// ---------------- decode MLP (warp per edge) ----------------
#define DEC_WARPS 8
__global__ __launch_bounds__(256)
void decode_kernel(const int* __restrict__ eli,
                   const float* __restrict__ Wm1, const float* __restrict__ bm1,
                   const float* __restrict__ Wm2, const float* __restrict__ bm2,
                   const float* __restrict__ Wm3, const float* __restrict__ bm3,
                   const float* __restrict__ Wm4, const float* __restrict__ bm4,
                   float* __restrict__ out) {
    __shared__ float sW1[128 * 64];
    __shared__ float es[DEC_WARPS][128];
    __shared__ float hs[DEC_WARPS][64];
    const int lane = threadIdx.x & 31;
    const int w = threadIdx.x >> 5;
    for (int i = threadIdx.x; i < 128 * 64; i += blockDim.x) sW1[i] = Wm1[i];
    __syncthreads();
    int gw = blockIdx.x * DEC_WARPS + w;
    int stride = gridDim.x * DEC_WARPS;
    for (int t = gw; t < L_EDGES; t += stride) {
        int s = eli[t], d = eli[L_EDGES + t];
        es[w][lane]      = g_z[(size_t)s * 64 + lane];
        es[w][lane + 32] = g_z[(size_t)s * 64 + lane + 32];
        es[w][lane + 64] = g_z[(size_t)d * 64 + lane];
        es[w][lane + 96] = g_z[(size_t)d * 64 + lane + 32];
        __syncwarp();
        float a0 = __ldg(&bm1[lane]), a1 = __ldg(&bm1[lane + 32]);
        #pragma unroll 8
        for (int k = 0; k < 128; k++) {
            float ev = es[w][k];
            a0 = fmaf(ev, sW1[k * 64 + lane], a0);
            a1 = fmaf(ev, sW1[k * 64 + lane + 32], a1);
        }
        __syncwarp();
        hs[w][lane] = fmaxf(a0, 0.f); hs[w][lane + 32] = fmaxf(a1, 0.f);
        __syncwarp();
        a0 = __ldg(&bm2[lane]); a1 = __ldg(&bm2[lane + 32]);
        #pragma unroll 8
        for (int k = 0; k < 64; k++) {
            float hv = hs[w][k];
            a0 = fmaf(hv, __ldg(&Wm2[k * 64 + lane]), a0);
            a1 = fmaf(hv, __ldg(&Wm2[k * 64 + lane + 32]), a1);
        }
        __syncwarp();
        hs[w][lane] = fmaxf(a0, 0.f); hs[w][lane + 32] = fmaxf(a1, 0.f);
        __syncwarp();
        a0 = __ldg(&bm3[lane]); a1 = __ldg(&bm3[lane + 32]);
        #pragma unroll 8
        for (int k = 0; k < 64; k++) {
            float hv = hs[w][k];
            a0 = fmaf(hv, __ldg(&Wm3[k * 64 + lane]), a0);
            a1 = fmaf(hv, __ldg(&Wm3[k * 64 + lane + 32]), a1);
        }
        __syncwarp();
        hs[w][lane] = fmaxf(a0, 0.f); hs[w][lane + 32] = fmaxf(a1, 0.f);
        __syncwarp();
        float o0 = 0.f, o1 = 0.f, o2 = 0.f;
        #pragma unroll
        for (int k = lane; k < 64; k += 32) {
            float hv = hs[w][k];
            o0 = fmaf(hv, __ldg(&Wm4[k * 3 + 0]), o0);
            o1 = fmaf(hv, __ldg(&Wm4[k * 3 + 1]), o1);
            o2 = fmaf(hv, __ldg(&Wm4[k * 3 + 2]), o2);
        }
        #pragma unroll
        for (int off = 16; off; off >>= 1) {
            o0 += __shfl_down_sync(0xffffffffu, o0, off);
            o1 += __shfl_down_sync(0xffffffffu, o1, off);
            o2 += __shfl_down_sync(0xffffffffu, o2, off);
        }
        if (lane == 0) {
            o0 += __ldg(&bm4[0]); o1 += __ldg(&bm4[1]); o2 += __ldg(&bm4[2]);
            int   idx  = 0;
            float best = o0;
            if (o1 > best) { best = o1; idx = 1; }
            if (o2 > best) { best = o2; idx = 2; }
            out[t]           = (float)idx;
            out[L_EDGES + t] = best;
            out[2 * L_EDGES + t * 3 + 0] = o0;
            out[2 * L_EDGES + t * 3 + 1] = o1;
            out[2 * L_EDGES + t * 3 + 2] = o2;
        }
        __syncwarp();
    }
}

// ---------------- host launch ----------------
static inline int cdiv(int a, int b) { return (a + b - 1) / b; }

extern "C" void kernel_launch(void* const* d_in, const int* in_sizes, int n_in,
                              void* d_out, int out_size) {
    const float* x   = (const float*)d_in[0];
    const int*   ei  = (const int*)d_in[1];
    const int*   hn  = (const int*)d_in[2];
    const int*   he  = (const int*)d_in[3];
    const int*   eli = (const int*)d_in[4];
    const float* W1  = (const float*)d_in[5];
    const float* b1  = (const float*)d_in[6];
    const float* W2  = (const float*)d_in[7];
    const float* a2s = (const float*)d_in[8];
    const float* a2d = (const float*)d_in[9];
    const float* b2  = (const float*)d_in[10];
    const float* W3  = (const float*)d_in[11];
    const float* a3s = (const float*)d_in[12];
    const float* a3d = (const float*)d_in[13];
    const float* b3  = (const float*)d_in[14];
    const float* Wm1 = (const float*)d_in[15];
    const float* bm1 = (const float*)d_in[16];
    const float* Wm2 = (const float*)d_in[17];
    const float* bm2 = (const float*)d_in[18];
    const float* Wm3 = (const float*)d_in[19];
    const float* bm3 = (const float*)d_in[20];
    const float* Wm4 = (const float*)d_in[21];
    const float* bm4 = (const float*)d_in[22];
    float* out = (float*)d_out;

    void *p_cnt_he, *p_cnt_nd, *p_cnt_g, *p_h0, *p_h1, *p_hg, *p_z;
    cudaGetSymbolAddress(&p_cnt_he, c_cnt_he);
    cudaGetSymbolAddress(&p_cnt_nd, c_cnt_nd);
    cudaGetSymbolAddress(&p_cnt_g,  c_cnt_g);
    cudaGetSymbolAddress(&p_h0, g_h0);
    cudaGetSymbolAddress(&p_h1, g_h1);
    cudaGetSymbolAddress(&p_hg, g_hg);
    cudaGetSymbolAddress(&p_z,  g_z);

    const int TB = 256;

    // ===== CSR builds =====
    cudaMemsetAsync(p_cnt_he, 0, sizeof(int) * N_HE, 0);
    cudaMemsetAsync(p_cnt_nd, 0, sizeof(int) * N_NODES, 0);
    cudaMemsetAsync(p_cnt_g,  0, sizeof(int) * N_NODES, 0);
    k_cnt_all<<<cdiv(N_PAIRS + E2, TB), TB>>>(hn, he, ei);
    k_scan3<<<3, 1024>>>();
    k_fill_all<<<cdiv(N_PAIRS + E2, TB), TB>>>(hn, he, ei);

    // ===== hypergraph conv =====
    sgemm<128, 128, 16, 8, 8><<<dim3(2, cdiv(N_NODES, 128)), 256>>>(x, W1, (float*)p_h0, N_NODES, 256, 128);
    k_hc_edge_gather<<<cdiv(N_HE * 32, TB), TB>>>();
    k_hc_node_gather<<<cdiv(N_NODES * 32, TB), TB>>>(b1);

    // ===== GAT layer 1 (256 -> 256) =====
    sgemm<128, 128, 16, 8, 8><<<dim3(2, cdiv(N_NODES, 128)), 256>>>((float*)p_h1, W2, (float*)p_hg, N_NODES, 256, 256);
    k_dots<256><<<cdiv(N_NODES * 32, TB), TB>>>(a2s, a2d);
    k_gat_aggr<256><<<cdiv(N_NODES * 32, TB), TB>>>(b2, (float*)p_h1);

    // ===== GAT layer 2 (256 -> 64) =====
    sgemm<128, 64, 16, 8, 4><<<dim3(1, cdiv(N_NODES, 128)), 256>>>((float*)p_h1, W3, (float*)p_hg, N_NODES, 64, 256);
    k_dots<64><<<cdiv(N_NODES * 32, TB), TB>>>(a3s, a3d);
    k_gat_aggr<64><<<cdiv(N_NODES * 32, TB), TB>>>(b3, (float*)p_z);

    // ===== decode MLP =====
    decode_kernel<<<740, TB>>>(eli, Wm1, bm1, Wm2, bm2, Wm3, bm3, Wm4, bm4, out);
}

// round 4
// speedup vs baseline: 1.8234x; 1.1421x over previous
#include <cuda_runtime.h>
#include <math.h>

#define N_NODES   50000
#define N_HE      20000
#define N_PAIRS   400000
#define E_EDGES   800000
#define E2        (E_EDGES + N_NODES)
#define L_EDGES   100000

// ---------------- scratch (device globals; no runtime allocation) ----------------
__device__ float g_h0[N_NODES * 256];
__device__ float g_m [N_HE    * 256];
__device__ float g_h1[N_NODES * 256];
__device__ float g_hg[N_NODES * 256];
__device__ float g_as[N_NODES];
__device__ float g_ad[N_NODES];
__device__ float g_z [N_NODES * 64];

__device__ int c_cnt_he[N_HE],    c_off_he[N_HE],    c_cur_he[N_HE],    c_val_he[N_PAIRS];
__device__ int c_cnt_nd[N_NODES], c_off_nd[N_NODES], c_cur_nd[N_NODES], c_val_nd[N_PAIRS];
__device__ int c_cnt_g [N_NODES], c_off_g [N_NODES], c_cur_g [N_NODES], c_val_g [E2];

typedef unsigned long long u64;

__device__ __forceinline__ float lrelu02(float x) { return x > 0.f ? x : 0.2f * x; }
__device__ __forceinline__ void f4add(float4& a, const float4 b) {
    a.x += b.x; a.y += b.y; a.z += b.z; a.w += b.w;
}
__device__ __forceinline__ void f4fma(float4& a, float w, const float4 b) {
    a.x = fmaf(w, b.x, a.x); a.y = fmaf(w, b.y, a.y);
    a.z = fmaf(w, b.z, a.z); a.w = fmaf(w, b.w, a.w);
}
// ---- packed fp32x2 (Blackwell FFMA2) ----
__device__ __forceinline__ u64 pk2(float lo, float hi) {
    u64 r; asm("mov.b64 %0, {%1, %2};" : "=l"(r) : "f"(lo), "f"(hi)); return r;
}
__device__ __forceinline__ u64 dup2(float x) { return pk2(x, x); }
__device__ __forceinline__ void unpk2(float& lo, float& hi, u64 v) {
    asm("mov.b64 {%0, %1}, %2;" : "=f"(lo), "=f"(hi) : "l"(v));
}
__device__ __forceinline__ void fma2(u64& d, u64 a, u64 b) {
    asm("fma.rn.f32x2 %0, %1, %2, %0;" : "+l"(d) : "l"(a), "l"(b));
}
__device__ __forceinline__ void add2(u64& d, u64 a) {
    asm("add.rn.f32x2 %0, %0, %1;" : "+l"(d) : "l"(a));
}

// ---------------- GEMM: C[M,N] = A[M,K] @ B[K,N], fp32, f32x2 core, double-buffered ----
template<int BM, int BN, int BK, int TM, int TN>
__global__ void __launch_bounds__((BM / TM) * (BN / TN))
sgemm(const float* __restrict__ A, const float* __restrict__ B, float* __restrict__ C,
      int M, int N, int K) {
    constexpr int NT = (BM / TM) * (BN / TN);
    constexpr int LA = BM * BK / 4 / NT;
    constexpr int LB = BK * BN / 4 / NT;
    __shared__ float As[2][BK][BM + 4];
    __shared__ float Bs[2][BK][BN];
    const int tid = threadIdx.x;
    const int tx = tid % (BN / TN);
    const int ty = tid / (BN / TN);
    const int rowBase = blockIdx.y * BM, colBase = blockIdx.x * BN;
    float4 ra[LA], rb[LB];

    auto loadA = [&](int k0) {
        #pragma unroll
        for (int s = 0; s < LA; s++) {
            int f = tid + s * NT;
            int r = f / (BK / 4), c = (f % (BK / 4)) * 4;
            int gr = rowBase + r;
            ra[s] = (gr < M) ? *(const float4*)&A[(size_t)gr * K + k0 + c]
                             : make_float4(0.f, 0.f, 0.f, 0.f);
        }
    };
    auto loadB = [&](int k0) {
        #pragma unroll
        for (int s = 0; s < LB; s++) {
            int f = tid + s * NT;
            int r = f / (BN / 4), c = (f % (BN / 4)) * 4;
            rb[s] = *(const float4*)&B[(size_t)(k0 + r) * N + colBase + c];
        }
    };
    auto stA = [&](int buf) {
        #pragma unroll
        for (int s = 0; s < LA; s++) {
            int f = tid + s * NT;
            int r = f / (BK / 4), c = (f % (BK / 4)) * 4;
            As[buf][c + 0][r] = ra[s].x; As[buf][c + 1][r] = ra[s].y;
            As[buf][c + 2][r] = ra[s].z; As[buf][c + 3][r] = ra[s].w;
        }
    };
    auto stB = [&](int buf) {
        #pragma unroll
        for (int s = 0; s < LB; s++) {
            int f = tid + s * NT;
            int r = f / (BN / 4), c = (f % (BN / 4)) * 4;
            *(float4*)&Bs[buf][r][c] = rb[s];
        }
    };

    u64 acc[TM][TN / 2];
    #pragma unroll
    for (int i = 0; i < TM; i++)
        #pragma unroll
        for (int j = 0; j < TN / 2; j++) acc[i][j] = 0ULL;

    loadA(0); loadB(0); stA(0); stB(0);
    __syncthreads();
    const int T = K / BK;
    int cur = 0;
    for (int t = 0; t < T; t++) {
        if (t + 1 < T) { loadA((t + 1) * BK); loadB((t + 1) * BK); }
        #pragma unroll
        for (int k = 0; k < BK; k++) {
            u64 a2[TM], b2[TN / 2];
            #pragma unroll
            for (int i = 0; i < TM; i++) a2[i] = dup2(As[cur][k][ty * TM + i]);
            #pragma unroll
            for (int j = 0; j < TN / 2; j++) {
                float2 bv = *(const float2*)&Bs[cur][k][tx * TN + 2 * j];
                b2[j] = pk2(bv.x, bv.y);
            }
            #pragma unroll
            for (int i = 0; i < TM; i++)
                #pragma unroll
                for (int j = 0; j < TN / 2; j++) fma2(acc[i][j], a2[i], b2[j]);
        }
        if (t + 1 < T) {
            stA(cur ^ 1); stB(cur ^ 1);
            __syncthreads();
            cur ^= 1;
        }
    }
    #pragma unroll
    for (int i = 0; i < TM; i++) {
        int gr = rowBase + ty * TM + i;
        if (gr < M) {
            #pragma unroll
            for (int j = 0; j < TN / 4; j++) {
                float4 v;
                unpk2(v.x, v.y, acc[i][2 * j]);
                unpk2(v.z, v.w, acc[i][2 * j + 1]);
                *(float4*)&C[(size_t)gr * N + colBase + tx * TN + 4 * j] = v;
            }
        }
    }
}

// ---------------- CSR build ----------------
__global__ void k_cnt_all(const int* __restrict__ hn, const int* __restrict__ he,
                          const int* __restrict__ ei) {
    int i = blockIdx.x * blockDim.x + threadIdx.x;
    if (i < N_PAIRS) {
        atomicAdd(&c_cnt_nd[hn[i]], 1);
        atomicAdd(&c_cnt_he[he[i]], 1);
    }
    int t = i - N_PAIRS;
    if (t >= 0 && t < E2) {
        int d = (t < E_EDGES) ? ei[E_EDGES + t] : (t - E_EDGES);
        atomicAdd(&c_cnt_g[d], 1);
    }
}

__device__ void scan_block(const int* __restrict__ in, int* __restrict__ off,
                           int* __restrict__ cur, int n) {
    const int tid = threadIdx.x;
    const int lane = tid & 31, wid = tid >> 5;
    __shared__ int wsums[32];
    __shared__ int s_tot;
    int carry = 0;
    for (int base = 0; base < n; base += 8192) {
        int i0 = base + tid * 8;
        int o[8], v[8];
        #pragma unroll
        for (int j = 0; j < 8; j++) o[j] = (i0 + j < n) ? in[i0 + j] : 0;
        v[0] = o[0];
        #pragma unroll
        for (int j = 1; j < 8; j++) v[j] = v[j - 1] + o[j];
        int tsum = v[7];
        int x = tsum;
        #pragma unroll
        for (int d = 1; d < 32; d <<= 1) {
            int y = __shfl_up_sync(0xffffffffu, x, d);
            if (lane >= d) x += y;
        }
        if (lane == 31) wsums[wid] = x;
        __syncthreads();
        if (wid == 0) {
            int y = wsums[lane], z = y;
            #pragma unroll
            for (int d = 1; d < 32; d <<= 1) {
                int u = __shfl_up_sync(0xffffffffu, z, d);
                if (lane >= d) z += u;
            }
            if (lane == 31) s_tot = z;
            wsums[lane] = z - y;
        }
        __syncthreads();
        int offv = carry + wsums[wid] + (x - tsum);
        #pragma unroll
        for (int j = 0; j < 8; j++) {
            if (i0 + j < n) {
                int e = offv + v[j] - o[j];
                off[i0 + j] = e;
                cur[i0 + j] = e;
            }
        }
        carry += s_tot;
        __syncthreads();
    }
}
__global__ void __launch_bounds__(1024) k_scan3() {
    if (blockIdx.x == 0)      scan_block(c_cnt_he, c_off_he, c_cur_he, N_HE);
    else if (blockIdx.x == 1) scan_block(c_cnt_nd, c_off_nd, c_cur_nd, N_NODES);
    else                      scan_block(c_cnt_g,  c_off_g,  c_cur_g,  N_NODES);
}

__global__ void k_fill_all(const int* __restrict__ hn, const int* __restrict__ he,
                           const int* __restrict__ ei) {
    int i = blockIdx.x * blockDim.x + threadIdx.x;
    if (i < N_PAIRS) {
        int n = hn[i], e = he[i];
        c_val_he[atomicAdd(&c_cur_he[e], 1)] = n;
        c_val_nd[atomicAdd(&c_cur_nd[n], 1)] = e;
    }
    int t = i - N_PAIRS;
    if (t >= 0 && t < E2) {
        int s, d;
        if (t < E_EDGES) { s = ei[t]; d = ei[E_EDGES + t]; } else { s = d = t - E_EDGES; }
        c_val_g[atomicAdd(&c_cur_g[d], 1)] = s;
    }
}

// ---------------- hypergraph conv (gather, float4, 2-deep pipeline) ----------------
__global__ void k_hc_edge_gather() {
    int gw = (blockIdx.x * blockDim.x + threadIdx.x) >> 5;
    int lane = threadIdx.x & 31;
    if (gw >= N_HE) return;
    int deg = c_cnt_he[gw], start = c_off_he[gw];
    float4 a0 = {0, 0, 0, 0}, a1 = {0, 0, 0, 0};
    int i = 0;
    for (; i + 2 <= deg; i += 2) {
        const float4* s0 = (const float4*)(g_h0 + (size_t)c_val_he[start + i] * 256);
        const float4* s1 = (const float4*)(g_h0 + (size_t)c_val_he[start + i + 1] * 256);
        float4 x00 = s0[lane], x01 = s0[lane + 32];
        float4 x10 = s1[lane], x11 = s1[lane + 32];
        f4add(a0, x00); f4add(a1, x01);
        f4add(a0, x10); f4add(a1, x11);
    }
    if (i < deg) {
        const float4* s0 = (const float4*)(g_h0 + (size_t)c_val_he[start + i] * 256);
        f4add(a0, s0[lane]); f4add(a1, s0[lane + 32]);
    }
    float binv = deg > 0 ? 1.f / (float)deg : 0.f;
    a0.x *= binv; a0.y *= binv; a0.z *= binv; a0.w *= binv;
    a1.x *= binv; a1.y *= binv; a1.z *= binv; a1.w *= binv;
    float4* dst = (float4*)(g_m + (size_t)gw * 256);
    dst[lane] = a0;
    dst[lane + 32] = a1;
}
__global__ void k_hc_node_gather(const float* __restrict__ b1) {
    int gw = (blockIdx.x * blockDim.x + threadIdx.x) >> 5;
    int lane = threadIdx.x & 31;
    if (gw >= N_NODES) return;
    int deg = c_cnt_nd[gw], start = c_off_nd[gw];
    float4 a0 = {0, 0, 0, 0}, a1 = {0, 0, 0, 0};
    int i = 0;
    for (; i + 2 <= deg; i += 2) {
        const float4* s0 = (const float4*)(g_m + (size_t)c_val_nd[start + i] * 256);
        const float4* s1 = (const float4*)(g_m + (size_t)c_val_nd[start + i + 1] * 256);
        float4 x00 = s0[lane], x01 = s0[lane + 32];
        float4 x10 = s1[lane], x11 = s1[lane + 32];
        f4add(a0, x00); f4add(a1, x01);
        f4add(a0, x10); f4add(a1, x11);
    }
    if (i < deg) {
        const float4* s0 = (const float4*)(g_m + (size_t)c_val_nd[start + i] * 256);
        f4add(a0, s0[lane]); f4add(a1, s0[lane + 32]);
    }
    float dinv = deg > 0 ? 1.f / (float)deg : 0.f;
    float4 bb0 = __ldg((const float4*)b1 + lane);
    float4 bb1 = __ldg((const float4*)b1 + lane + 32);
    float4 r0, r1;
    r0.x = fmaxf(a0.x * dinv + bb0.x, 0.f); r0.y = fmaxf(a0.y * dinv + bb0.y, 0.f);
    r0.z = fmaxf(a0.z * dinv + bb0.z, 0.f); r0.w = fmaxf(a0.w * dinv + bb0.w, 0.f);
    r1.x = fmaxf(a1.x * dinv + bb1.x, 0.f); r1.y = fmaxf(a1.y * dinv + bb1.y, 0.f);
    r1.z = fmaxf(a1.z * dinv + bb1.z, 0.f); r1.w = fmaxf(a1.w * dinv + bb1.w, 0.f);
    float4* dst = (float4*)(g_h1 + (size_t)gw * 256);
    dst[lane] = r0;
    dst[lane + 32] = r1;
}

// ---------------- GAT ----------------
template <int C>
__global__ void k_dots(const float* __restrict__ a_s, const float* __restrict__ a_d) {
    int gw = (blockIdx.x * blockDim.x + threadIdx.x) >> 5;
    int lane = threadIdx.x & 31;
    if (gw >= N_NODES) return;
    float s0 = 0.f, s1 = 0.f;
    const float4* h = (const float4*)(g_hg + (size_t)gw * C);
    #pragma unroll
    for (int j = lane; j < C / 4; j += 32) {
        float4 v = h[j];
        float4 as4 = __ldg((const float4*)a_s + j);
        float4 ad4 = __ldg((const float4*)a_d + j);
        s0 += v.x * as4.x + v.y * as4.y + v.z * as4.z + v.w * as4.w;
        s1 += v.x * ad4.x + v.y * ad4.y + v.z * ad4.z + v.w * ad4.w;
    }
    #pragma unroll
    for (int off = 16; off; off >>= 1) {
        s0 += __shfl_down_sync(0xffffffffu, s0, off);
        s1 += __shfl_down_sync(0xffffffffu, s1, off);
    }
    if (lane == 0) { g_as[gw] = s0; g_ad[gw] = s1; }
}

template <int C>
__global__ void k_gat_aggr(const float* __restrict__ bias, float* __restrict__ dst) {
    int gw = (blockIdx.x * blockDim.x + threadIdx.x) >> 5;
    int lane = threadIdx.x & 31;
    if (gw >= N_NODES) return;
    int deg = c_cnt_g[gw], start = c_off_g[gw];
    float adst = g_ad[gw];
    float mx = -1e30f;
    for (int i = lane; i < deg; i += 32)
        mx = fmaxf(mx, lrelu02(g_as[c_val_g[start + i]] + adst));
    #pragma unroll
    for (int off = 16; off; off >>= 1)
        mx = fmaxf(mx, __shfl_xor_sync(0xffffffffu, mx, off));
    float sm = 0.f;
    for (int i = lane; i < deg; i += 32)
        sm += expf(lrelu02(g_as[c_val_g[start + i]] + adst) - mx);
    #pragma unroll
    for (int off = 16; off; off >>= 1)
        sm += __shfl_xor_sync(0xffffffffu, sm, off);
    float inv = 1.f / (sm + 1e-16f);
    if constexpr (C == 256) {
        float4 a0 = {0, 0, 0, 0}, a1 = {0, 0, 0, 0};
        int i = 0;
        for (; i + 2 <= deg; i += 2) {
            int s0 = c_val_g[start + i], s1 = c_val_g[start + i + 1];
            float w0 = expf(lrelu02(g_as[s0] + adst) - mx) * inv;
            float w1 = expf(lrelu02(g_as[s1] + adst) - mx) * inv;
            const float4* h0p = (const float4*)(g_hg + (size_t)s0 * 256);
            const float4* h1p = (const float4*)(g_hg + (size_t)s1 * 256);
            float4 x00 = h0p[lane], x01 = h0p[lane + 32];
            float4 x10 = h1p[lane], x11 = h1p[lane + 32];
            f4fma(a0, w0, x00); f4fma(a1, w0, x01);
            f4fma(a0, w1, x10); f4fma(a1, w1, x11);
        }
        if (i < deg) {
            int s0 = c_val_g[start + i];
            float w0 = expf(lrelu02(g_as[s0] + adst) - mx) * inv;
            const float4* h0p = (const float4*)(g_hg + (size_t)s0 * 256);
            f4fma(a0, w0, h0p[lane]); f4fma(a1, w0, h0p[lane + 32]);
        }
        float4 bb0 = __ldg((const float4*)bias + lane);
        float4 bb1 = __ldg((const float4*)bias + lane + 32);
        float4 r0, r1;
        r0.x = fmaxf(a0.x + bb0.x, 0.f); r0.y = fmaxf(a0.y + bb0.y, 0.f);
        r0.z = fmaxf(a0.z + bb0.z, 0.f); r0.w = fmaxf(a0.w + bb0.w, 0.f);
        r1.x = fmaxf(a1.x + bb1.x, 0.f); r1.y = fmaxf(a1.y + bb1.y, 0.f);
        r1.z = fmaxf(a1.z + bb1.z, 0.f); r1.w = fmaxf(a1.w + bb1.w, 0.f);
        float4* o = (float4*)(dst + (size_t)gw * 256);
        o[lane] = r0;
        o[lane + 32] = r1;
    } else {
        float2 acc = {0, 0};
        int i = 0;
        for (; i + 2 <= deg; i += 2) {
            int s0 = c_val_g[start + i], s1 = c_val_g[start + i + 1];
            float w0 = expf(lrelu02(g_as[s0] + adst) - mx) * inv;
            float w1 = expf(lrelu02(g_as[s1] + adst) - mx) * inv;
            float2 x0 = *(const float2*)(g_hg + (size_t)s0 * 64 + 2 * lane);
            float2 x1 = *(const float2*)(g_hg + (size_t)s1 * 64 + 2 * lane);
            acc.x = fmaf(w0, x0.x, acc.x); acc.y = fmaf(w0, x0.y, acc.y);
            acc.x = fmaf(w1, x1.x, acc.x); acc.y = fmaf(w1, x1.y, acc.y);
        }
        if (i < deg) {
            int s0 = c_val_g[start + i];
            float w0 = expf(lrelu02(g_as[s0] + adst) - mx) * inv;
            float2 x0 = *(const float2*)(g_hg + (size_t)s0 * 64 + 2 * lane);
            acc.x = fmaf(w0, x0.x, acc.x); acc.y = fmaf(w0, x0.y, acc.y);
        }
        float2 bb = *(const float2*)(bias + 2 * lane);
        float2 r;
        r.x = fmaxf(acc.x + bb.x, 0.f);
        r.y = fmaxf(acc.y + bb.y, 0.f);
        *(float2*)(dst + (size_t)gw * 64 + 2 * lane) = r;
    }
}

// ---------------- decode MLP (warp per edge, f32x2, channel pairs per lane) --------
#define DEC_WARPS 8
__global__ __launch_bounds__(256)
void decode_kernel(const int* __restrict__ eli,
                   const float* __restrict__ Wm1, const float* __restrict__ bm1,
                   const float* __restrict__ Wm2, const float* __restrict__ bm2,
                   const float* __restrict__ Wm3, const float* __restrict__ bm3,
                   const float* __restrict__ Wm4, const float* __restrict__ bm4,
                   float* __restrict__ out) {
    __shared__ float sW1[128 * 64];
    __shared__ float sW2[64 * 64];
    __shared__ float sW3[64 * 64];
    __shared__ float es[DEC_WARPS][128];
    __shared__ float hs[DEC_WARPS][64];
    const int lane = threadIdx.x & 31;
    const int w = threadIdx.x >> 5;
    for (int i = threadIdx.x; i < 128 * 64; i += blockDim.x) sW1[i] = Wm1[i];
    for (int i = threadIdx.x; i < 64 * 64; i += blockDim.x) { sW2[i] = Wm2[i]; sW3[i] = Wm3[i]; }
    __syncthreads();
    int gw = blockIdx.x * DEC_WARPS + w;
    int stride = gridDim.x * DEC_WARPS;
    const int c2 = 2 * lane;
    for (int t = gw; t < L_EDGES; t += stride) {
        int s = eli[t], d = eli[L_EDGES + t];
        *(float2*)&es[w][c2]      = *(const float2*)&g_z[(size_t)s * 64 + c2];
        *(float2*)&es[w][64 + c2] = *(const float2*)&g_z[(size_t)d * 64 + c2];
        __syncwarp();
        // ---- layer 1: 128 -> 64 ----
        {
            float2 bb = *(const float2*)&bm1[c2];
            u64 a0 = pk2(bb.x, bb.y), a1 = 0ULL, a2 = 0ULL, a3 = 0ULL;
            #pragma unroll
            for (int k = 0; k < 128; k += 4) {
                float4 ev = *(const float4*)&es[w][k];
                float2 w0 = *(const float2*)&sW1[(k + 0) * 64 + c2];
                float2 w1 = *(const float2*)&sW1[(k + 1) * 64 + c2];
                float2 w2 = *(const float2*)&sW1[(k + 2) * 64 + c2];
                float2 w3 = *(const float2*)&sW1[(k + 3) * 64 + c2];
                fma2(a0, dup2(ev.x), pk2(w0.x, w0.y));
                fma2(a1, dup2(ev.y), pk2(w1.x, w1.y));
                fma2(a2, dup2(ev.z), pk2(w2.x, w2.y));
                fma2(a3, dup2(ev.w), pk2(w3.x, w3.y));
            }
            add2(a0, a1); add2(a2, a3); add2(a0, a2);
            float r0, r1; unpk2(r0, r1, a0);
            __syncwarp();
            hs[w][c2] = fmaxf(r0, 0.f); hs[w][c2 + 1] = fmaxf(r1, 0.f);
            __syncwarp();
        }
        // ---- layers 2,3: 64 -> 64 ----
        #pragma unroll
        for (int L = 0; L < 2; L++) {
            const float* Wl = L == 0 ? sW2 : sW3;
            const float* bl = L == 0 ? bm2 : bm3;
            float2 bb = *(const float2*)&bl[c2];
            u64 a0 = pk2(bb.x, bb.y), a1 = 0ULL, a2 = 0ULL, a3 = 0ULL;
            #pragma unroll
            for (int k = 0; k < 64; k += 4) {
                float4 ev = *(const float4*)&hs[w][k];
                float2 w0 = *(const float2*)&Wl[(k + 0) * 64 + c2];
                float2 w1 = *(const float2*)&Wl[(k + 1) * 64 + c2];
                float2 w2 = *(const float2*)&Wl[(k + 2) * 64 + c2];
                float2 w3 = *(const float2*)&Wl[(k + 3) * 64 + c2];
                fma2(a0, dup2(ev.x), pk2(w0.x, w0.y));
                fma2(a1, dup2(ev.y), pk2(w1.x, w1.y));
                fma2(a2, dup2(ev.z), pk2(w2.x, w2.y));
                fma2(a3, dup2(ev.w), pk2(w3.x, w3.y));
            }
            add2(a0, a1); add2(a2, a3); add2(a0, a2);
            float r0, r1; unpk2(r0, r1, a0);
            __syncwarp();
            hs[w][c2] = fmaxf(r0, 0.f); hs[w][c2 + 1] = fmaxf(r1, 0.f);
            __syncwarp();
        }
        // ---- layer 4: 64 -> 3 ----
        float2 hv = *(const float2*)&hs[w][c2];
        float o0 = hv.x * __ldg(&Wm4[c2 * 3 + 0]) + hv.y * __ldg(&Wm4[(c2 + 1) * 3 + 0]);
        float o1 = hv.x * __ldg(&Wm4[c2 * 3 + 1]) + hv.y * __ldg(&Wm4[(c2 + 1) * 3 + 1]);
        float o2 = hv.x * __ldg(&Wm4[c2 * 3 + 2]) + hv.y * __ldg(&Wm4[(c2 + 1) * 3 + 2]);
        #pragma unroll
        for (int off = 16; off; off >>= 1) {
            o0 += __shfl_down_sync(0xffffffffu, o0, off);
            o1 += __shfl_down_sync(0xffffffffu, o1, off);
            o2 += __shfl_down_sync(0xffffffffu, o2, off);
        }
        if (lane == 0) {
            o0 += __ldg(&bm4[0]); o1 += __ldg(&bm4[1]); o2 += __ldg(&bm4[2]);
            int   idx  = 0;
            float best = o0;
            if (o1 > best) { best = o1; idx = 1; }
            if (o2 > best) { best = o2; idx = 2; }
            out[t]           = (float)idx;
            out[L_EDGES + t] = best;
            out[2 * L_EDGES + t * 3 + 0] = o0;
            out[2 * L_EDGES + t * 3 + 1] = o1;
            out[2 * L_EDGES + t * 3 + 2] = o2;
        }
        __syncwarp();
    }
}

// ---------------- host launch ----------------
static inline int cdiv(int a, int b) { return (a + b - 1) / b; }

extern "C" void kernel_launch(void* const* d_in, const int* in_sizes, int n_in,
                              void* d_out, int out_size) {
    const float* x   = (const float*)d_in[0];
    const int*   ei  = (const int*)d_in[1];
    const int*   hn  = (const int*)d_in[2];
    const int*   he  = (const int*)d_in[3];
    const int*   eli = (const int*)d_in[4];
    const float* W1  = (const float*)d_in[5];
    const float* b1  = (const float*)d_in[6];
    const float* W2  = (const float*)d_in[7];
    const float* a2s = (const float*)d_in[8];
    const float* a2d = (const float*)d_in[9];
    const float* b2  = (const float*)d_in[10];
    const float* W3  = (const float*)d_in[11];
    const float* a3s = (const float*)d_in[12];
    const float* a3d = (const float*)d_in[13];
    const float* b3  = (const float*)d_in[14];
    const float* Wm1 = (const float*)d_in[15];
    const float* bm1 = (const float*)d_in[16];
    const float* Wm2 = (const float*)d_in[17];
    const float* bm2 = (const float*)d_in[18];
    const float* Wm3 = (const float*)d_in[19];
    const float* bm3 = (const float*)d_in[20];
    const float* Wm4 = (const float*)d_in[21];
    const float* bm4 = (const float*)d_in[22];
    float* out = (float*)d_out;

    void *p_cnt_he, *p_cnt_nd, *p_cnt_g, *p_h0, *p_h1, *p_hg, *p_z;
    cudaGetSymbolAddress(&p_cnt_he, c_cnt_he);
    cudaGetSymbolAddress(&p_cnt_nd, c_cnt_nd);
    cudaGetSymbolAddress(&p_cnt_g,  c_cnt_g);
    cudaGetSymbolAddress(&p_h0, g_h0);
    cudaGetSymbolAddress(&p_h1, g_h1);
    cudaGetSymbolAddress(&p_hg, g_hg);
    cudaGetSymbolAddress(&p_z,  g_z);

    const int TB = 256;

    // ===== CSR builds =====
    cudaMemsetAsync(p_cnt_he, 0, sizeof(int) * N_HE, 0);
    cudaMemsetAsync(p_cnt_nd, 0, sizeof(int) * N_NODES, 0);
    cudaMemsetAsync(p_cnt_g,  0, sizeof(int) * N_NODES, 0);
    k_cnt_all<<<cdiv(N_PAIRS + E2, TB), TB>>>(hn, he, ei);
    k_scan3<<<3, 1024>>>();
    k_fill_all<<<cdiv(N_PAIRS + E2, TB), TB>>>(hn, he, ei);

    // ===== hypergraph conv =====
    sgemm<128, 128, 16, 8, 8><<<dim3(2, cdiv(N_NODES, 128)), 256>>>(x, W1, (float*)p_h0, N_NODES, 256, 128);
    k_hc_edge_gather<<<cdiv(N_HE * 32, TB), TB>>>();
    k_hc_node_gather<<<cdiv(N_NODES * 32, TB), TB>>>(b1);

    // ===== GAT layer 1 (256 -> 256) =====
    sgemm<128, 128, 16, 8, 8><<<dim3(2, cdiv(N_NODES, 128)), 256>>>((float*)p_h1, W2, (float*)p_hg, N_NODES, 256, 256);
    k_dots<256><<<cdiv(N_NODES * 32, TB), TB>>>(a2s, a2d);
    k_gat_aggr<256><<<cdiv(N_NODES * 32, TB), TB>>>(b2, (float*)p_h1);

    // ===== GAT layer 2 (256 -> 64) =====
    sgemm<128, 64, 16, 8, 4><<<dim3(1, cdiv(N_NODES, 128)), 256>>>((float*)p_h1, W3, (float*)p_hg, N_NODES, 64, 256);
    k_dots<64><<<cdiv(N_NODES * 32, TB), TB>>>(a3s, a3d);
    k_gat_aggr<64><<<cdiv(N_NODES * 32, TB), TB>>>(b3, (float*)p_z);

    // ===== decode MLP =====
    decode_kernel<<<740, TB>>>(eli, Wm1, bm1, Wm2, bm2, Wm3, bm3, Wm4, bm4, out);
}

// round 5
// speedup vs baseline: 1.9536x; 1.0714x over previous
#include <cuda_runtime.h>
#include <math.h>

#define N_NODES   50000
#define N_HE      20000
#define N_PAIRS   400000
#define E_EDGES   800000
#define E2        (E_EDGES + N_NODES)
#define L_EDGES   100000

// ---------------- scratch (device globals; no runtime allocation) ----------------
__device__ float g_h0[N_NODES * 256];   // reused: m128 (20000x128) pre-GEMM hyperedge sums
__device__ float g_m [N_HE    * 256];   // hyperedge messages post-GEMM
__device__ float g_h1[N_NODES * 256];   // activations (reused across layers)
__device__ float g_hg[N_NODES * 256];   // GEMM output features
__device__ float g_as[N_NODES];
__device__ float g_ad[N_NODES];
__device__ float g_z [N_NODES * 64];

__device__ int c_cnt_he[N_HE],    c_off_he[N_HE],    c_cur_he[N_HE],    c_val_he[N_PAIRS];
__device__ int c_cnt_nd[N_NODES], c_off_nd[N_NODES], c_cur_nd[N_NODES], c_val_nd[N_PAIRS];
__device__ int c_cnt_g [N_NODES], c_off_g [N_NODES], c_cur_g [N_NODES], c_val_g [E2];

typedef unsigned long long u64;

__device__ __forceinline__ float lrelu02(float x) { return x > 0.f ? x : 0.2f * x; }
__device__ __forceinline__ void f4add(float4& a, const float4 b) {
    a.x += b.x; a.y += b.y; a.z += b.z; a.w += b.w;
}
__device__ __forceinline__ void f4fma(float4& a, float w, const float4 b) {
    a.x = fmaf(w, b.x, a.x); a.y = fmaf(w, b.y, a.y);
    a.z = fmaf(w, b.z, a.z); a.w = fmaf(w, b.w, a.w);
}
// ---- packed fp32x2 (Blackwell FFMA2) ----
__device__ __forceinline__ u64 pk2(float lo, float hi) {
    u64 r; asm("mov.b64 %0, {%1, %2};" : "=l"(r) : "f"(lo), "f"(hi)); return r;
}
__device__ __forceinline__ u64 dup2(float x) { return pk2(x, x); }
__device__ __forceinline__ void unpk2(float& lo, float& hi, u64 v) {
    asm("mov.b64 {%0, %1}, %2;" : "=f"(lo), "=f"(hi) : "l"(v));
}
__device__ __forceinline__ void fma2(u64& d, u64 a, u64 b) {
    asm("fma.rn.f32x2 %0, %1, %2, %0;" : "+l"(d) : "l"(a), "l"(b));
}
__device__ __forceinline__ void add2(u64& d, u64 a) {
    asm("add.rn.f32x2 %0, %0, %1;" : "+l"(d) : "l"(a));
}

// ---------------- GEMM: C[M,N] = A[M,K] @ B[K,N], fp32, f32x2 core, double-buffered ----
template<int BM, int BN, int BK, int TM, int TN>
__global__ void __launch_bounds__((BM / TM) * (BN / TN))
sgemm(const float* __restrict__ A, const float* __restrict__ B, float* __restrict__ C,
      int M, int N, int K) {
    constexpr int NT = (BM / TM) * (BN / TN);
    constexpr int LA = BM * BK / 4 / NT;
    constexpr int LB = BK * BN / 4 / NT;
    __shared__ float As[2][BK][BM + 4];   // row stride 132 floats = 528B (16B-multiple)
    __shared__ float Bs[2][BK][BN];
    const int tid = threadIdx.x;
    const int tx = tid % (BN / TN);
    const int ty = tid / (BN / TN);
    const int rowBase = blockIdx.y * BM, colBase = blockIdx.x * BN;
    float4 ra[LA], rb[LB];

    auto loadA = [&](int k0) {
        #pragma unroll
        for (int s = 0; s < LA; s++) {
            int f = tid + s * NT;
            int r = f / (BK / 4), c = (f % (BK / 4)) * 4;
            int gr = rowBase + r;
            ra[s] = (gr < M) ? *(const float4*)&A[(size_t)gr * K + k0 + c]
                             : make_float4(0.f, 0.f, 0.f, 0.f);
        }
    };
    auto loadB = [&](int k0) {
        #pragma unroll
        for (int s = 0; s < LB; s++) {
            int f = tid + s * NT;
            int r = f / (BN / 4), c = (f % (BN / 4)) * 4;
            rb[s] = *(const float4*)&B[(size_t)(k0 + r) * N + colBase + c];
        }
    };
    auto stA = [&](int buf) {
        #pragma unroll
        for (int s = 0; s < LA; s++) {
            int f = tid + s * NT;
            int r = f / (BK / 4), c = (f % (BK / 4)) * 4;
            As[buf][c + 0][r] = ra[s].x; As[buf][c + 1][r] = ra[s].y;
            As[buf][c + 2][r] = ra[s].z; As[buf][c + 3][r] = ra[s].w;
        }
    };
    auto stB = [&](int buf) {
        #pragma unroll
        for (int s = 0; s < LB; s++) {
            int f = tid + s * NT;
            int r = f / (BN / 4), c = (f % (BN / 4)) * 4;
            *(float4*)&Bs[buf][r][c] = rb[s];
        }
    };

    u64 acc[TM][TN / 2];
    #pragma unroll
    for (int i = 0; i < TM; i++)
        #pragma unroll
        for (int j = 0; j < TN / 2; j++) acc[i][j] = 0ULL;

    loadA(0); loadB(0); stA(0); stB(0);
    __syncthreads();
    const int T = K / BK;
    int cur = 0;
    for (int t = 0; t < T; t++) {
        if (t + 1 < T) { loadA((t + 1) * BK); loadB((t + 1) * BK); }
        #pragma unroll
        for (int k = 0; k < BK; k++) {
            // vectorized fragment loads: LDS.128 only
            float af[TM], bf[TN];
            #pragma unroll
            for (int i = 0; i < TM; i += 4)
                *(float4*)&af[i] = *(const float4*)&As[cur][k][ty * TM + i];
            #pragma unroll
            for (int j = 0; j < TN; j += 4)
                *(float4*)&bf[j] = *(const float4*)&Bs[cur][k][tx * TN + j];
            u64 a2[TM], b2[TN / 2];
            #pragma unroll
            for (int i = 0; i < TM; i++) a2[i] = dup2(af[i]);
            #pragma unroll
            for (int j = 0; j < TN / 2; j++) b2[j] = pk2(bf[2 * j], bf[2 * j + 1]);
            #pragma unroll
            for (int i = 0; i < TM; i++)
                #pragma unroll
                for (int j = 0; j < TN / 2; j++) fma2(acc[i][j], a2[i], b2[j]);
        }
        if (t + 1 < T) {
            stA(cur ^ 1); stB(cur ^ 1);
            __syncthreads();
            cur ^= 1;
        }
    }
    #pragma unroll
    for (int i = 0; i < TM; i++) {
        int gr = rowBase + ty * TM + i;
        if (gr < M) {
            #pragma unroll
            for (int j = 0; j < TN / 4; j++) {
                float4 v;
                unpk2(v.x, v.y, acc[i][2 * j]);
                unpk2(v.z, v.w, acc[i][2 * j + 1]);
                *(float4*)&C[(size_t)gr * N + colBase + tx * TN + 4 * j] = v;
            }
        }
    }
}

// ---------------- CSR build ----------------
__global__ void k_cnt_all(const int* __restrict__ hn, const int* __restrict__ he,
                          const int* __restrict__ ei) {
    int i = blockIdx.x * blockDim.x + threadIdx.x;
    if (i < N_PAIRS) {
        atomicAdd(&c_cnt_nd[hn[i]], 1);
        atomicAdd(&c_cnt_he[he[i]], 1);
    }
    int t = i - N_PAIRS;
    if (t >= 0 && t < E2) {
        int d = (t < E_EDGES) ? ei[E_EDGES + t] : (t - E_EDGES);
        atomicAdd(&c_cnt_g[d], 1);
    }
}

__device__ void scan_block(const int* __restrict__ in, int* __restrict__ off,
                           int* __restrict__ cur, int n) {
    const int tid = threadIdx.x;
    const int lane = tid & 31, wid = tid >> 5;
    __shared__ int wsums[32];
    __shared__ int s_tot;
    int carry = 0;
    for (int base = 0; base < n; base += 8192) {
        int i0 = base + tid * 8;
        int o[8], v[8];
        #pragma unroll
        for (int j = 0; j < 8; j++) o[j] = (i0 + j < n) ? in[i0 + j] : 0;
        v[0] = o[0];
        #pragma unroll
        for (int j = 1; j < 8; j++) v[j] = v[j - 1] + o[j];
        int tsum = v[7];
        int x = tsum;
        #pragma unroll
        for (int d = 1; d < 32; d <<= 1) {
            int y = __shfl_up_sync(0xffffffffu, x, d);
            if (lane >= d) x += y;
        }
        if (lane == 31) wsums[wid] = x;
        __syncthreads();
        if (wid == 0) {
            int y = wsums[lane], z = y;
            #pragma unroll
            for (int d = 1; d < 32; d <<= 1) {
                int u = __shfl_up_sync(0xffffffffu, z, d);
                if (lane >= d) z += u;
            }
            if (lane == 31) s_tot = z;
            wsums[lane] = z - y;
        }
        __syncthreads();
        int offv = carry + wsums[wid] + (x - tsum);
        #pragma unroll
        for (int j = 0; j < 8; j++) {
            if (i0 + j < n) {
                int e = offv + v[j] - o[j];
                off[i0 + j] = e;
                cur[i0 + j] = e;
            }
        }
        carry += s_tot;
        __syncthreads();
    }
}
__global__ void __launch_bounds__(1024) k_scan3() {
    if (blockIdx.x == 0)      scan_block(c_cnt_he, c_off_he, c_cur_he, N_HE);
    else if (blockIdx.x == 1) scan_block(c_cnt_nd, c_off_nd, c_cur_nd, N_NODES);
    else                      scan_block(c_cnt_g,  c_off_g,  c_cur_g,  N_NODES);
}

__global__ void k_fill_all(const int* __restrict__ hn, const int* __restrict__ he,
                           const int* __restrict__ ei) {
    int i = blockIdx.x * blockDim.x + threadIdx.x;
    if (i < N_PAIRS) {
        int n = hn[i], e = he[i];
        c_val_he[atomicAdd(&c_cur_he[e], 1)] = n;
        c_val_nd[atomicAdd(&c_cur_nd[n], 1)] = e;
    }
    int t = i - N_PAIRS;
    if (t >= 0 && t < E2) {
        int s, d;
        if (t < E_EDGES) { s = ei[t]; d = ei[E_EDGES + t]; } else { s = d = t - E_EDGES; }
        c_val_g[atomicAdd(&c_cur_g[d], 1)] = s;
    }
}

// ---------------- hypergraph conv ----------------
// NEW: gather raw x (128-dim) per hyperedge, scale by Binv. GEMM applied after (linearity).
__global__ void k_hc_edge_gather128(const float* __restrict__ x) {
    int gw = (blockIdx.x * blockDim.x + threadIdx.x) >> 5;
    int lane = threadIdx.x & 31;
    if (gw >= N_HE) return;
    int deg = c_cnt_he[gw], start = c_off_he[gw];
    float4 a = {0, 0, 0, 0};
    int i = 0;
    for (; i + 2 <= deg; i += 2) {
        const float4* s0 = (const float4*)(x + (size_t)c_val_he[start + i] * 128);
        const float4* s1 = (const float4*)(x + (size_t)c_val_he[start + i + 1] * 128);
        float4 x0 = s0[lane], x1 = s1[lane];
        f4add(a, x0); f4add(a, x1);
    }
    if (i < deg) {
        const float4* s0 = (const float4*)(x + (size_t)c_val_he[start + i] * 128);
        f4add(a, s0[lane]);
    }
    float binv = deg > 0 ? 1.f / (float)deg : 0.f;
    a.x *= binv; a.y *= binv; a.z *= binv; a.w *= binv;
    ((float4*)(g_h0 + (size_t)gw * 128))[lane] = a;   // g_h0 reused as m128 [N_HE x 128]
}
// node gather over 256-dim hyperedge messages + Dinv + bias + relu
__global__ void k_hc_node_gather(const float* __restrict__ b1) {
    int gw = (blockIdx.x * blockDim.x + threadIdx.x) >> 5;
    int lane = threadIdx.x & 31;
    if (gw >= N_NODES) return;
    int deg = c_cnt_nd[gw], start = c_off_nd[gw];
    float4 a0 = {0, 0, 0, 0}, a1 = {0, 0, 0, 0};
    int i = 0;
    for (; i + 2 <= deg; i += 2) {
        const float4* s0 = (const float4*)(g_m + (size_t)c_val_nd[start + i] * 256);
        const float4* s1 = (const float4*)(g_m + (size_t)c_val_nd[start + i + 1] * 256);
        float4 x00 = s0[lane], x01 = s0[lane + 32];
        float4 x10 = s1[lane], x11 = s1[lane + 32];
        f4add(a0, x00); f4add(a1, x01);
        f4add(a0, x10); f4add(a1, x11);
    }
    if (i < deg) {
        const float4* s0 = (const float4*)(g_m + (size_t)c_val_nd[start + i] * 256);
        f4add(a0, s0[lane]); f4add(a1, s0[lane + 32]);
    }
    float dinv = deg > 0 ? 1.f / (float)deg : 0.f;
    float4 bb0 = __ldg((const float4*)b1 + lane);
    float4 bb1 = __ldg((const float4*)b1 + lane + 32);
    float4 r0, r1;
    r0.x = fmaxf(a0.x * dinv + bb0.x, 0.f); r0.y = fmaxf(a0.y * dinv + bb0.y, 0.f);
    r0.z = fmaxf(a0.z * dinv + bb0.z, 0.f); r0.w = fmaxf(a0.w * dinv + bb0.w, 0.f);
    r1.x = fmaxf(a1.x * dinv + bb1.x, 0.f); r1.y = fmaxf(a1.y * dinv + bb1.y, 0.f);
    r1.z = fmaxf(a1.z * dinv + bb1.z, 0.f); r1.w = fmaxf(a1.w * dinv + bb1.w, 0.f);
    float4* dst = (float4*)(g_h1 + (size_t)gw * 256);
    dst[lane] = r0;
    dst[lane + 32] = r1;
}

// ---------------- GAT ----------------
template <int C>
__global__ void k_dots(const float* __restrict__ a_s, const float* __restrict__ a_d) {
    int gw = (blockIdx.x * blockDim.x + threadIdx.x) >> 5;
    int lane = threadIdx.x & 31;
    if (gw >= N_NODES) return;
    float s0 = 0.f, s1 = 0.f;
    const float4* h = (const float4*)(g_hg + (size_t)gw * C);
    #pragma unroll
    for (int j = lane; j < C / 4; j += 32) {
        float4 v = h[j];
        float4 as4 = __ldg((const float4*)a_s + j);
        float4 ad4 = __ldg((const float4*)a_d + j);
        s0 += v.x * as4.x + v.y * as4.y + v.z * as4.z + v.w * as4.w;
        s1 += v.x * ad4.x + v.y * ad4.y + v.z * ad4.z + v.w * ad4.w;
    }
    #pragma unroll
    for (int off = 16; off; off >>= 1) {
        s0 += __shfl_down_sync(0xffffffffu, s0, off);
        s1 += __shfl_down_sync(0xffffffffu, s1, off);
    }
    if (lane == 0) { g_as[gw] = s0; g_ad[gw] = s1; }
}

template <int C>
__global__ void k_gat_aggr(const float* __restrict__ bias, float* __restrict__ dst) {
    int gw = (blockIdx.x * blockDim.x + threadIdx.x) >> 5;
    int lane = threadIdx.x & 31;
    if (gw >= N_NODES) return;
    int deg = c_cnt_g[gw], start = c_off_g[gw];
    float adst = g_ad[gw];
    float mx = -1e30f;
    for (int i = lane; i < deg; i += 32)
        mx = fmaxf(mx, lrelu02(g_as[c_val_g[start + i]] + adst));
    #pragma unroll
    for (int off = 16; off; off >>= 1)
        mx = fmaxf(mx, __shfl_xor_sync(0xffffffffu, mx, off));
    float sm = 0.f;
    for (int i = lane; i < deg; i += 32)
        sm += expf(lrelu02(g_as[c_val_g[start + i]] + adst) - mx);
    #pragma unroll
    for (int off = 16; off; off >>= 1)
        sm += __shfl_xor_sync(0xffffffffu, sm, off);
    float inv = 1.f / (sm + 1e-16f);
    if constexpr (C == 256) {
        float4 a0 = {0, 0, 0, 0}, a1 = {0, 0, 0, 0};
        int i = 0;
        for (; i + 2 <= deg; i += 2) {
            int s0 = c_val_g[start + i], s1 = c_val_g[start + i + 1];
            float w0 = expf(lrelu02(g_as[s0] + adst) - mx) * inv;
            float w1 = expf(lrelu02(g_as[s1] + adst) - mx) * inv;
            const float4* h0p = (const float4*)(g_hg + (size_t)s0 * 256);
            const float4* h1p = (const float4*)(g_hg + (size_t)s1 * 256);
            float4 x00 = h0p[lane], x01 = h0p[lane + 32];
            float4 x10 = h1p[lane], x11 = h1p[lane + 32];
            f4fma(a0, w0, x00); f4fma(a1, w0, x01);
            f4fma(a0, w1, x10); f4fma(a1, w1, x11);
        }
        if (i < deg) {
            int s0 = c_val_g[start + i];
            float w0 = expf(lrelu02(g_as[s0] + adst) - mx) * inv;
            const float4* h0p = (const float4*)(g_hg + (size_t)s0 * 256);
            f4fma(a0, w0, h0p[lane]); f4fma(a1, w0, h0p[lane + 32]);
        }
        float4 bb0 = __ldg((const float4*)bias + lane);
        float4 bb1 = __ldg((const float4*)bias + lane + 32);
        float4 r0, r1;
        r0.x = fmaxf(a0.x + bb0.x, 0.f); r0.y = fmaxf(a0.y + bb0.y, 0.f);
        r0.z = fmaxf(a0.z + bb0.z, 0.f); r0.w = fmaxf(a0.w + bb0.w, 0.f);
        r1.x = fmaxf(a1.x + bb1.x, 0.f); r1.y = fmaxf(a1.y + bb1.y, 0.f);
        r1.z = fmaxf(a1.z + bb1.z, 0.f); r1.w = fmaxf(a1.w + bb1.w, 0.f);
        float4* o = (float4*)(dst + (size_t)gw * 256);
        o[lane] = r0;
        o[lane + 32] = r1;
    } else {
        float2 acc = {0, 0};
        int i = 0;
        for (; i + 2 <= deg; i += 2) {
            int s0 = c_val_g[start + i], s1 = c_val_g[start + i + 1];
            float w0 = expf(lrelu02(g_as[s0] + adst) - mx) * inv;
            float w1 = expf(lrelu02(g_as[s1] + adst) - mx) * inv;
            float2 x0 = *(const float2*)(g_hg + (size_t)s0 * 64 + 2 * lane);
            float2 x1 = *(const float2*)(g_hg + (size_t)s1 * 64 + 2 * lane);
            acc.x = fmaf(w0, x0.x, acc.x); acc.y = fmaf(w0, x0.y, acc.y);
            acc.x = fmaf(w1, x1.x, acc.x); acc.y = fmaf(w1, x1.y, acc.y);
        }
        if (i < deg) {
            int s0 = c_val_g[start + i];
            float w0 = expf(lrelu02(g_as[s0] + adst) - mx) * inv;
            float2 x0 = *(const float2*)(g_hg + (size_t)s0 * 64 + 2 * lane);
            acc.x = fmaf(w0, x0.x, acc.x); acc.y = fmaf(w0, x0.y, acc.y);
        }
        float2 bb = *(const float2*)(bias + 2 * lane);
        float2 r;
        r.x = fmaxf(acc.x + bb.x, 0.f);
        r.y = fmaxf(acc.y + bb.y, 0.f);
        *(float2*)(dst + (size_t)gw * 64 + 2 * lane) = r;
    }
}

// ---------------- decode MLP (warp per edge, f32x2, channel pairs per lane) --------
#define DEC_WARPS 8
__global__ __launch_bounds__(256)
void decode_kernel(const int* __restrict__ eli,
                   const float* __restrict__ Wm1, const float* __restrict__ bm1,
                   const float* __restrict__ Wm2, const float* __restrict__ bm2,
                   const float* __restrict__ Wm3, const float* __restrict__ bm3,
                   const float* __restrict__ Wm4, const float* __restrict__ bm4,
                   float* __restrict__ out) {
    __shared__ float sW1[128 * 64];
    __shared__ float sW2[64 * 64];
    __shared__ float sW3[64 * 64];
    __shared__ float es[DEC_WARPS][128];
    __shared__ float hs[DEC_WARPS][64];
    const int lane = threadIdx.x & 31;
    const int w = threadIdx.x >> 5;
    for (int i = threadIdx.x; i < 128 * 64; i += blockDim.x) sW1[i] = Wm1[i];
    for (int i = threadIdx.x; i < 64 * 64; i += blockDim.x) { sW2[i] = Wm2[i]; sW3[i] = Wm3[i]; }
    __syncthreads();
    int gw = blockIdx.x * DEC_WARPS + w;
    int stride = gridDim.x * DEC_WARPS;
    const int c2 = 2 * lane;
    for (int t = gw; t < L_EDGES; t += stride) {
        int s = eli[t], d = eli[L_EDGES + t];
        *(float2*)&es[w][c2]      = *(const float2*)&g_z[(size_t)s * 64 + c2];
        *(float2*)&es[w][64 + c2] = *(const float2*)&g_z[(size_t)d * 64 + c2];
        __syncwarp();
        {
            float2 bb = *(const float2*)&bm1[c2];
            u64 a0 = pk2(bb.x, bb.y), a1 = 0ULL, a2 = 0ULL, a3 = 0ULL;
            #pragma unroll
            for (int k = 0; k < 128; k += 4) {
                float4 ev = *(const float4*)&es[w][k];
                float2 w0 = *(const float2*)&sW1[(k + 0) * 64 + c2];
                float2 w1 = *(const float2*)&sW1[(k + 1) * 64 + c2];
                float2 w2 = *(const float2*)&sW1[(k + 2) * 64 + c2];
                float2 w3 = *(const float2*)&sW1[(k + 3) * 64 + c2];
                fma2(a0, dup2(ev.x), pk2(w0.x, w0.y));
                fma2(a1, dup2(ev.y), pk2(w1.x, w1.y));
                fma2(a2, dup2(ev.z), pk2(w2.x, w2.y));
                fma2(a3, dup2(ev.w), pk2(w3.x, w3.y));
            }
            add2(a0, a1); add2(a2, a3); add2(a0, a2);
            float r0, r1; unpk2(r0, r1, a0);
            __syncwarp();
            hs[w][c2] = fmaxf(r0, 0.f); hs[w][c2 + 1] = fmaxf(r1, 0.f);
            __syncwarp();
        }
        #pragma unroll
        for (int L = 0; L < 2; L++) {
            const float* Wl = L == 0 ? sW2 : sW3;
            const float* bl = L == 0 ? bm2 : bm3;
            float2 bb = *(const float2*)&bl[c2];
            u64 a0 = pk2(bb.x, bb.y), a1 = 0ULL, a2 = 0ULL, a3 = 0ULL;
            #pragma unroll
            for (int k = 0; k < 64; k += 4) {
                float4 ev = *(const float4*)&hs[w][k];
                float2 w0 = *(const float2*)&Wl[(k + 0) * 64 + c2];
                float2 w1 = *(const float2*)&Wl[(k + 1) * 64 + c2];
                float2 w2 = *(const float2*)&Wl[(k + 2) * 64 + c2];
                float2 w3 = *(const float2*)&Wl[(k + 3) * 64 + c2];
                fma2(a0, dup2(ev.x), pk2(w0.x, w0.y));
                fma2(a1, dup2(ev.y), pk2(w1.x, w1.y));
                fma2(a2, dup2(ev.z), pk2(w2.x, w2.y));
                fma2(a3, dup2(ev.w), pk2(w3.x, w3.y));
            }
            add2(a0, a1); add2(a2, a3); add2(a0, a2);
            float r0, r1; unpk2(r0, r1, a0);
            __syncwarp();
            hs[w][c2] = fmaxf(r0, 0.f); hs[w][c2 + 1] = fmaxf(r1, 0.f);
            __syncwarp();
        }
        float2 hv = *(const float2*)&hs[w][c2];
        float o0 = hv.x * __ldg(&Wm4[c2 * 3 + 0]) + hv.y * __ldg(&Wm4[(c2 + 1) * 3 + 0]);
        float o1 = hv.x * __ldg(&Wm4[c2 * 3 + 1]) + hv.y * __ldg(&Wm4[(c2 + 1) * 3 + 1]);
        float o2 = hv.x * __ldg(&Wm4[c2 * 3 + 2]) + hv.y * __ldg(&Wm4[(c2 + 1) * 3 + 2]);
        #pragma unroll
        for (int off = 16; off; off >>= 1) {
            o0 += __shfl_down_sync(0xffffffffu, o0, off);
            o1 += __shfl_down_sync(0xffffffffu, o1, off);
            o2 += __shfl_down_sync(0xffffffffu, o2, off);
        }
        if (lane == 0) {
            o0 += __ldg(&bm4[0]); o1 += __ldg(&bm4[1]); o2 += __ldg(&bm4[2]);
            int   idx  = 0;
            float best = o0;
            if (o1 > best) { best = o1; idx = 1; }
            if (o2 > best) { best = o2; idx = 2; }
            out[t]           = (float)idx;
            out[L_EDGES + t] = best;
            out[2 * L_EDGES + t * 3 + 0] = o0;
            out[2 * L_EDGES + t * 3 + 1] = o1;
            out[2 * L_EDGES + t * 3 + 2] = o2;
        }
        __syncwarp();
    }
}

// ---------------- host launch ----------------
static inline int cdiv(int a, int b) { return (a + b - 1) / b; }

extern "C" void kernel_launch(void* const* d_in, const int* in_sizes, int n_in,
                              void* d_out, int out_size) {
    const float* x   = (const float*)d_in[0];
    const int*   ei  = (const int*)d_in[1];
    const int*   hn  = (const int*)d_in[2];
    const int*   he  = (const int*)d_in[3];
    const int*   eli = (const int*)d_in[4];
    const float* W1  = (const float*)d_in[5];
    const float* b1  = (const float*)d_in[6];
    const float* W2  = (const float*)d_in[7];
    const float* a2s = (const float*)d_in[8];
    const float* a2d = (const float*)d_in[9];
    const float* b2  = (const float*)d_in[10];
    const float* W3  = (const float*)d_in[11];
    const float* a3s = (const float*)d_in[12];
    const float* a3d = (const float*)d_in[13];
    const float* b3  = (const float*)d_in[14];
    const float* Wm1 = (const float*)d_in[15];
    const float* bm1 = (const float*)d_in[16];
    const float* Wm2 = (const float*)d_in[17];
    const float* bm2 = (const float*)d_in[18];
    const float* Wm3 = (const float*)d_in[19];
    const float* bm3 = (const float*)d_in[20];
    const float* Wm4 = (const float*)d_in[21];
    const float* bm4 = (const float*)d_in[22];
    float* out = (float*)d_out;

    void *p_cnt_he, *p_cnt_nd, *p_cnt_g, *p_h0, *p_h1, *p_hg, *p_z, *p_m;
    cudaGetSymbolAddress(&p_cnt_he, c_cnt_he);
    cudaGetSymbolAddress(&p_cnt_nd, c_cnt_nd);
    cudaGetSymbolAddress(&p_cnt_g,  c_cnt_g);
    cudaGetSymbolAddress(&p_h0, g_h0);
    cudaGetSymbolAddress(&p_h1, g_h1);
    cudaGetSymbolAddress(&p_hg, g_hg);
    cudaGetSymbolAddress(&p_z,  g_z);
    cudaGetSymbolAddress(&p_m,  g_m);

    const int TB = 256;

    // ===== CSR builds =====
    cudaMemsetAsync(p_cnt_he, 0, sizeof(int) * N_HE, 0);
    cudaMemsetAsync(p_cnt_nd, 0, sizeof(int) * N_NODES, 0);
    cudaMemsetAsync(p_cnt_g,  0, sizeof(int) * N_NODES, 0);
    k_cnt_all<<<cdiv(N_PAIRS + E2, TB), TB>>>(hn, he, ei);
    k_scan3<<<3, 1024>>>();
    k_fill_all<<<cdiv(N_PAIRS + E2, TB), TB>>>(hn, he, ei);

    // ===== hypergraph conv: gather x (128d) -> GEMM on hyperedges -> node gather =====
    k_hc_edge_gather128<<<cdiv(N_HE * 32, TB), TB>>>(x);
    sgemm<128, 128, 16, 8, 8><<<dim3(2, cdiv(N_HE, 128)), 256>>>((float*)p_h0, W1, (float*)p_m, N_HE, 256, 128);
    k_hc_node_gather<<<cdiv(N_NODES * 32, TB), TB>>>(b1);

    // ===== GAT layer 1 (256 -> 256) =====
    sgemm<128, 128, 16, 8, 8><<<dim3(2, cdiv(N_NODES, 128)), 256>>>((float*)p_h1, W2, (float*)p_hg, N_NODES, 256, 256);
    k_dots<256><<<cdiv(N_NODES * 32, TB), TB>>>(a2s, a2d);
    k_gat_aggr<256><<<cdiv(N_NODES * 32, TB), TB>>>(b2, (float*)p_h1);

    // ===== GAT layer 2 (256 -> 64) =====
    sgemm<128, 64, 16, 8, 4><<<dim3(1, cdiv(N_NODES, 128)), 256>>>((float*)p_h1, W3, (float*)p_hg, N_NODES, 64, 256);
    k_dots<64><<<cdiv(N_NODES * 32, TB), TB>>>(a3s, a3d);
    k_gat_aggr<64><<<cdiv(N_NODES * 32, TB), TB>>>(b3, (float*)p_z);

    // ===== decode MLP =====
    decode_kernel<<<740, TB>>>(eli, Wm1, bm1, Wm2, bm2, Wm3, bm3, Wm4, bm4, out);
}